// round 1
// baseline (speedup 1.0000x reference)
#include <cuda_runtime.h>
#include <math.h>

#define BB 64
#define SS 196
#define EE 768
#define HH 4
#define HD 192
#define GRID14 14
#define BSROWS (BB*SS)      /* 12544 */
#define SE (SS*EE)          /* 150528 */
#define LN_EPS 1e-5f

// ---------------- scratch (static device allocations; no cudaMalloc) -------
__device__ float g_patches[BSROWS*EE];
__device__ float g_emb[BSROWS*EE];      // skip1
__device__ float g_h[BSROWS*EE];        // LN1 output
__device__ float g_q[BSROWS*EE];
__device__ float g_k[BSROWS*EE];
__device__ float g_v[BSROWS*EE];
__device__ float g_scores[BB*HH*SS*SS];
__device__ float g_attno[BSROWS*EE];
__device__ float g_res[BSROWS*EE];      // skip1 + proj (pre-LN2)
__device__ float g_stats[BB*2];         // mean, rstd per batch

// ---------------- patch extraction ----------------------------------------
// patches[b, s, e'] with s = gy*14+gx, e' = c*256 + py*16 + px
__global__ void patch_kernel(const float* __restrict__ x, float* __restrict__ out) {
    int idx = blockIdx.x * blockDim.x + threadIdx.x;
    if (idx >= BSROWS * EE) return;
    int col = idx % EE;
    int row = idx / EE;
    int b = row / SS, s = row % SS;
    int gy = s / GRID14, gx = s % GRID14;
    int c = col >> 8;            // /256
    int r = col & 255;
    int py = r >> 4, px = r & 15;
    out[idx] = x[(((size_t)b * 3 + c) * 224 + (gy * 16 + py)) * 224 + (gx * 16 + px)];
}

// ---------------- generic SGEMM: C[M,N] = A[M,K] * B[N,K]^T + bias (+skip) --
// BM=BN=64, BK=16, 256 threads, 4x4 micro-tile. Requires M%64==0, N%64==0, K%16==0.
template <bool HAS_SKIP>
__global__ __launch_bounds__(256)
void gemm_nt(const float* __restrict__ A, const float* __restrict__ Bm,
             const float* __restrict__ bias, const float* __restrict__ skip,
             float* __restrict__ C, int M, int N, int K) {
    __shared__ float As[16][64];
    __shared__ float Bs[16][64];
    int bx = blockIdx.x;   // N tile
    int by = blockIdx.y;   // M tile
    int tid = threadIdx.x;
    int tx = tid & 15, ty = tid >> 4;

    const float* Ab = A + (size_t)(by * 64) * K;
    const float* Bb = Bm + (size_t)(bx * 64) * K;

    float acc[4][4];
#pragma unroll
    for (int i = 0; i < 4; i++)
#pragma unroll
        for (int j = 0; j < 4; j++) acc[i][j] = 0.f;

    int lr = tid >> 2;           // 0..63
    int lc = (tid & 3) * 4;      // 0,4,8,12

    for (int k0 = 0; k0 < K; k0 += 16) {
        float4 a = *(const float4*)(Ab + (size_t)lr * K + k0 + lc);
        float4 b = *(const float4*)(Bb + (size_t)lr * K + k0 + lc);
        As[lc + 0][lr] = a.x; As[lc + 1][lr] = a.y; As[lc + 2][lr] = a.z; As[lc + 3][lr] = a.w;
        Bs[lc + 0][lr] = b.x; Bs[lc + 1][lr] = b.y; Bs[lc + 2][lr] = b.z; Bs[lc + 3][lr] = b.w;
        __syncthreads();
#pragma unroll
        for (int k = 0; k < 16; k++) {
            float4 av = *(const float4*)&As[k][ty * 4];
            float4 bv = *(const float4*)&Bs[k][tx * 4];
            acc[0][0] += av.x * bv.x; acc[0][1] += av.x * bv.y; acc[0][2] += av.x * bv.z; acc[0][3] += av.x * bv.w;
            acc[1][0] += av.y * bv.x; acc[1][1] += av.y * bv.y; acc[1][2] += av.y * bv.z; acc[1][3] += av.y * bv.w;
            acc[2][0] += av.z * bv.x; acc[2][1] += av.z * bv.y; acc[2][2] += av.z * bv.z; acc[2][3] += av.z * bv.w;
            acc[3][0] += av.w * bv.x; acc[3][1] += av.w * bv.y; acc[3][2] += av.w * bv.z; acc[3][3] += av.w * bv.w;
        }
        __syncthreads();
    }

#pragma unroll
    for (int i = 0; i < 4; i++) {
        int m = by * 64 + ty * 4 + i;
#pragma unroll
        for (int j = 0; j < 4; j++) {
            int n = bx * 64 + tx * 4 + j;
            float v = acc[i][j] + bias[n];
            if (HAS_SKIP) v += skip[(size_t)m * N + n];
            C[(size_t)m * N + n] = v;
        }
    }
}

// ---------------- LayerNorm over [S,E] per batch ---------------------------
__global__ __launch_bounds__(512)
void ln_reduce(const float* __restrict__ x, float* __restrict__ stats) {
    int b = blockIdx.x;
    const float4* p = (const float4*)(x + (size_t)b * SE);
    float s = 0.f, s2 = 0.f;
    for (int i = threadIdx.x; i < SE / 4; i += blockDim.x) {
        float4 v = p[i];
        s  += v.x + v.y + v.z + v.w;
        s2 += v.x * v.x + v.y * v.y + v.z * v.z + v.w * v.w;
    }
    __shared__ float sh[16], sh2[16];
#pragma unroll
    for (int o = 16; o > 0; o >>= 1) {
        s  += __shfl_xor_sync(0xffffffffu, s, o);
        s2 += __shfl_xor_sync(0xffffffffu, s2, o);
    }
    int w = threadIdx.x >> 5;
    if ((threadIdx.x & 31) == 0) { sh[w] = s; sh2[w] = s2; }
    __syncthreads();
    if (threadIdx.x == 0) {
        float ts = 0.f, ts2 = 0.f;
        for (int i = 0; i < 16; i++) { ts += sh[i]; ts2 += sh2[i]; }
        float mean = ts / (float)SE;
        float var  = ts2 / (float)SE - mean * mean;
        stats[2 * b] = mean;
        stats[2 * b + 1] = rsqrtf(var + LN_EPS);
    }
}

__global__ void ln_apply(const float* __restrict__ x, const float* __restrict__ w,
                         const float* __restrict__ bias, const float* __restrict__ stats,
                         float* __restrict__ out) {
    int idx = blockIdx.x * blockDim.x + threadIdx.x;
    if (idx >= BB * SE) return;
    int b = idx / SE;
    int i = idx - b * SE;
    float mean = stats[2 * b], rstd = stats[2 * b + 1];
    out[idx] = (x[idx] - mean) * rstd * w[i] + bias[i];
}

// ---------------- attention: scores = (Q K^T) / sqrt(HD) -------------------
// grid (7, 7, B*H), block 256 (16x16), tile 32x32, 2x2 micro, BK=16 (HD=192)
__global__ __launch_bounds__(256)
void attn_scores(const float* __restrict__ q, const float* __restrict__ k,
                 float* __restrict__ scores) {
    int bh = blockIdx.z;
    int b = bh / HH, h = bh % HH;
    const float* qb = q + (size_t)(b * SS) * EE + h * HD;
    const float* kb = k + (size_t)(b * SS) * EE + h * HD;
    float* sb = scores + (size_t)bh * SS * SS;

    __shared__ float Qs[16][32];
    __shared__ float Ks[16][32];
    int tid = threadIdx.x;
    int tx = tid & 15, ty = tid >> 4;
    int m0 = blockIdx.y * 32, n0 = blockIdx.x * 32;

    float a00 = 0.f, a01 = 0.f, a10 = 0.f, a11 = 0.f;
    int lr = tid >> 4;   // 0..15
    int lc = tid & 15;   // 0..15

    for (int k0 = 0; k0 < HD; k0 += 16) {
#pragma unroll
        for (int j = 0; j < 2; j++) {
            int r = lr + j * 16;
            int m = m0 + r;
            Qs[lc][r] = (m < SS) ? qb[(size_t)m * EE + k0 + lc] : 0.f;
            int n = n0 + r;
            Ks[lc][r] = (n < SS) ? kb[(size_t)n * EE + k0 + lc] : 0.f;
        }
        __syncthreads();
#pragma unroll
        for (int kk = 0; kk < 16; kk++) {
            float q0 = Qs[kk][ty * 2], q1 = Qs[kk][ty * 2 + 1];
            float k0v = Ks[kk][tx * 2], k1v = Ks[kk][tx * 2 + 1];
            a00 += q0 * k0v; a01 += q0 * k1v;
            a10 += q1 * k0v; a11 += q1 * k1v;
        }
        __syncthreads();
    }
    const float scale = 0.07216878364870322f;  // 1/sqrt(192)
    int m = m0 + ty * 2, n = n0 + tx * 2;
    if (m < SS) {
        if (n < SS)     sb[(size_t)m * SS + n]     = a00 * scale;
        if (n + 1 < SS) sb[(size_t)m * SS + n + 1] = a01 * scale;
    }
    if (m + 1 < SS) {
        if (n < SS)     sb[(size_t)(m + 1) * SS + n]     = a10 * scale;
        if (n + 1 < SS) sb[(size_t)(m + 1) * SS + n + 1] = a11 * scale;
    }
}

// ---------------- softmax over rows of scores ------------------------------
__global__ __launch_bounds__(128)
void softmax_k(float* __restrict__ sc) {
    size_t row = blockIdx.x;
    float* p = sc + row * SS;
    int tid = threadIdx.x;
    __shared__ float redm[4], reds[4];

    float mx = -1e30f;
    for (int i = tid; i < SS; i += 128) mx = fmaxf(mx, p[i]);
#pragma unroll
    for (int o = 16; o > 0; o >>= 1) mx = fmaxf(mx, __shfl_xor_sync(0xffffffffu, mx, o));
    if ((tid & 31) == 0) redm[tid >> 5] = mx;
    __syncthreads();
    mx = fmaxf(fmaxf(redm[0], redm[1]), fmaxf(redm[2], redm[3]));

    float sum = 0.f;
    for (int i = tid; i < SS; i += 128) {
        float e = __expf(p[i] - mx);
        p[i] = e;
        sum += e;
    }
#pragma unroll
    for (int o = 16; o > 0; o >>= 1) sum += __shfl_xor_sync(0xffffffffu, sum, o);
    if ((tid & 31) == 0) reds[tid >> 5] = sum;
    __syncthreads();
    sum = reds[0] + reds[1] + reds[2] + reds[3];
    float inv = 1.0f / sum;
    for (int i = tid; i < SS; i += 128) p[i] *= inv;
}

// ---------------- O = attn @ V  (NN gemm, per bh) --------------------------
// grid (6, 7, B*H), block 256, tile 32x32 (M=S rows, N=HD cols), BK=16 over S
__global__ __launch_bounds__(256)
void attn_out(const float* __restrict__ attn, const float* __restrict__ v,
              float* __restrict__ o) {
    int bh = blockIdx.z;
    int b = bh / HH, h = bh % HH;
    const float* ab = attn + (size_t)bh * SS * SS;
    const float* vb = v + (size_t)(b * SS) * EE + h * HD;
    float* ob = o + (size_t)(b * SS) * EE + h * HD;

    __shared__ float As[16][32];
    __shared__ float Vs[16][32];
    int tid = threadIdx.x;
    int tx = tid & 15, ty = tid >> 4;
    int m0 = blockIdx.y * 32, n0 = blockIdx.x * 32;

    float a00 = 0.f, a01 = 0.f, a10 = 0.f, a11 = 0.f;
    int lr = tid >> 4, lc = tid & 15;
    int vr = tid >> 5, vc = tid & 31;

    for (int k0 = 0; k0 < SS; k0 += 16) {
#pragma unroll
        for (int j = 0; j < 2; j++) {
            int r = lr + j * 16;
            int m = m0 + r;
            As[lc][r] = (m < SS && (k0 + lc) < SS) ? ab[(size_t)m * SS + k0 + lc] : 0.f;
        }
#pragma unroll
        for (int j = 0; j < 2; j++) {
            int kk = vr + j * 8;
            Vs[kk][vc] = ((k0 + kk) < SS) ? vb[(size_t)(k0 + kk) * EE + n0 + vc] : 0.f;
        }
        __syncthreads();
#pragma unroll
        for (int kk = 0; kk < 16; kk++) {
            float p0 = As[kk][ty * 2], p1 = As[kk][ty * 2 + 1];
            float v0 = Vs[kk][tx * 2], v1 = Vs[kk][tx * 2 + 1];
            a00 += p0 * v0; a01 += p0 * v1;
            a10 += p1 * v0; a11 += p1 * v1;
        }
        __syncthreads();
    }
    int m = m0 + ty * 2, n = n0 + tx * 2;  // n always < 192
    if (m < SS) {
        ob[(size_t)m * EE + n]     = a00;
        ob[(size_t)m * EE + n + 1] = a01;
    }
    if (m + 1 < SS) {
        ob[(size_t)(m + 1) * EE + n]     = a10;
        ob[(size_t)(m + 1) * EE + n + 1] = a11;
    }
}

// ---------------- launch ----------------------------------------------------
extern "C" void kernel_launch(void* const* d_in, const int* in_sizes, int n_in,
                              void* d_out, int out_size) {
    const float* x      = (const float*)d_in[0];
    const float* conv_w = (const float*)d_in[1];
    const float* conv_b = (const float*)d_in[2];
    const float* wq     = (const float*)d_in[3];
    const float* bq     = (const float*)d_in[4];
    const float* wk     = (const float*)d_in[5];
    const float* bk     = (const float*)d_in[6];
    const float* wv     = (const float*)d_in[7];
    const float* bv     = (const float*)d_in[8];
    const float* wo     = (const float*)d_in[9];
    const float* bo     = (const float*)d_in[10];
    const float* ln1w   = (const float*)d_in[11];
    const float* ln1b   = (const float*)d_in[12];
    const float* ln2w   = (const float*)d_in[13];
    const float* ln2b   = (const float*)d_in[14];
    float* out = (float*)d_out;

    float *patches, *emb, *h, *q, *k, *v, *sc, *ao, *res, *stats;
    cudaGetSymbolAddress((void**)&patches, g_patches);
    cudaGetSymbolAddress((void**)&emb,     g_emb);
    cudaGetSymbolAddress((void**)&h,       g_h);
    cudaGetSymbolAddress((void**)&q,       g_q);
    cudaGetSymbolAddress((void**)&k,       g_k);
    cudaGetSymbolAddress((void**)&v,       g_v);
    cudaGetSymbolAddress((void**)&sc,      g_scores);
    cudaGetSymbolAddress((void**)&ao,      g_attno);
    cudaGetSymbolAddress((void**)&res,     g_res);
    cudaGetSymbolAddress((void**)&stats,   g_stats);

    dim3 gemm_grid(EE / 64, BSROWS / 64);   // (12, 196)

    // 1. patch extraction
    patch_kernel<<<(BSROWS * EE + 255) / 256, 256>>>(x, patches);
    // 2. patch embedding GEMM
    gemm_nt<false><<<gemm_grid, 256>>>(patches, conv_w, conv_b, nullptr, emb,
                                       BSROWS, EE, EE);
    // 3. LN1
    ln_reduce<<<BB, 512>>>(emb, stats);
    ln_apply<<<(BB * SE + 255) / 256, 256>>>(emb, ln1w, ln1b, stats, h);
    // 4. QKV
    gemm_nt<false><<<gemm_grid, 256>>>(h, wq, bq, nullptr, q, BSROWS, EE, EE);
    gemm_nt<false><<<gemm_grid, 256>>>(h, wk, bk, nullptr, k, BSROWS, EE, EE);
    gemm_nt<false><<<gemm_grid, 256>>>(h, wv, bv, nullptr, v, BSROWS, EE, EE);
    // 5. attention
    attn_scores<<<dim3(7, 7, BB * HH), 256>>>(q, k, sc);
    softmax_k<<<BB * HH * SS, 128>>>(sc);
    attn_out<<<dim3(HD / 32, 7, BB * HH), 256>>>(sc, v, ao);
    // 6. output projection + residual
    gemm_nt<true><<<gemm_grid, 256>>>(ao, wo, bo, emb, res, BSROWS, EE, EE);
    // 7. LN2 -> d_out
    ln_reduce<<<BB, 512>>>(res, stats);
    ln_apply<<<(BB * SE + 255) / 256, 256>>>(res, ln2w, ln2b, stats, out);
}

// round 5
// speedup vs baseline: 3.7108x; 3.7108x over previous
#include <cuda_runtime.h>
#include <math.h>
#include <stdint.h>

#define BB 64
#define SS 196
#define EE 768
#define HH 4
#define HD 192
#define GRID14 14
#define BSROWS (BB*SS)      /* 12544 */
#define SE (SS*EE)          /* 150528 */
#define LN_EPS 1e-5f

// ---------------- scratch (static device arrays; no cudaMalloc) -------------
__device__ float g_patches[BSROWS*EE];
__device__ float g_emb[BSROWS*EE];      // skip1
__device__ float g_h[BSROWS*EE];        // LN1 output
__device__ float g_q[BSROWS*EE];
__device__ float g_k[BSROWS*EE];
__device__ float g_v[BSROWS*EE];
__device__ float g_scores[BB*HH*SS*SS];
__device__ float g_attno[BSROWS*EE];
__device__ float g_res[BSROWS*EE];      // skip1 + proj (pre-LN2)
__device__ float g_stats[BB*2];         // mean, rstd per batch

// =================== helpers ================================================
__device__ __forceinline__ uint32_t smem_u32(const void* p) {
    uint32_t a;
    asm("{ .reg .u64 t; cvta.to.shared.u64 t, %1; cvt.u32.u64 %0, t; }"
        : "=r"(a) : "l"(p));
    return a;
}

__device__ __forceinline__ void cp16(void* smem_dst, const void* gmem_src) {
    uint32_t s = smem_u32(smem_dst);
    asm volatile("cp.async.cg.shared.global [%0], [%1], 16;"
                 :: "r"(s), "l"(gmem_src) : "memory");
}
#define CP_COMMIT() asm volatile("cp.async.commit_group;" ::: "memory")
#define CP_WAIT0()  asm volatile("cp.async.wait_group 0;" ::: "memory")
#define CP_WAIT1()  asm volatile("cp.async.wait_group 1;" ::: "memory")

// mma.sync m16n8k8 tf32: D(16x8,f32) += A(16x8,tf32) * B(8x8,tf32)
__device__ __forceinline__ void mma_tf32(float* c, const uint32_t* a,
                                         const uint32_t* b) {
    asm volatile(
        "mma.sync.aligned.m16n8k8.row.col.f32.tf32.tf32.f32 "
        "{%0,%1,%2,%3}, {%4,%5,%6,%7}, {%8,%9}, {%0,%1,%2,%3};"
        : "+f"(c[0]), "+f"(c[1]), "+f"(c[2]), "+f"(c[3])
        : "r"(a[0]), "r"(a[1]), "r"(a[2]), "r"(a[3]), "r"(b[0]), "r"(b[1]));
}

// =================== tf32 tensor-core GEMM ==================================
// C[M,N] = A[M,K] * B[N,K]^T + bias (+skip).
// CTA tile 128x128, BK=32 floats, 256 threads (8 warps, 2x4), double-buffered
// cp.async staging. Requires M%128==0, N%128==0, K%32==0.
#define LDSD 36                       /* padded row stride (floats) */
#define TILEF (128 * LDSD)            /* floats per (A or B) buffer */
#define GEMM_SMEM_BYTES (4 * TILEF * 4)   /* 73728 B */

template <bool HAS_SKIP>
__global__ __launch_bounds__(256)
void gemm_mma(const float* __restrict__ A, const float* __restrict__ Bm,
              const float* __restrict__ bias, const float* __restrict__ skip,
              float* __restrict__ C, int M, int N, int K) {
    extern __shared__ float sm[];
    float* Asm = sm;                  // [2][TILEF]
    float* Bsm = sm + 2 * TILEF;      // [2][TILEF]

    const int tid = threadIdx.x;
    const int wid = tid >> 5, lane = tid & 31;
    const int wm = wid >> 2;          // 0..1  (64-row slab)
    const int wn = wid & 3;           // 0..3  (32-col slab)
    const int gl = lane >> 2;         // group (0..7)
    const int tg = lane & 3;          // thread-in-group (0..3)

    const int m0 = blockIdx.y * 128, n0 = blockIdx.x * 128;
    const float* Ab = A + (size_t)m0 * K;
    const float* Bb = Bm + (size_t)n0 * K;

    const int srow = tid >> 3;        // 0..31 handled 4x -> 128 rows
    const int sc4  = tid & 7;         // float4 within the 32-float row

    float acc[4][4][4];
#pragma unroll
    for (int i = 0; i < 4; i++)
#pragma unroll
        for (int j = 0; j < 4; j++)
#pragma unroll
            for (int r = 0; r < 4; r++) acc[i][j][r] = 0.f;

    const int NC = K >> 5;            // 24 chunks

    // stage chunk c into buffer buf
    auto stage = [&](int c, int buf) {
        const float* ag = Ab + c * 32;
        const float* bg = Bb + c * 32;
        float* ad = Asm + buf * TILEF;
        float* bd = Bsm + buf * TILEF;
#pragma unroll
        for (int i = 0; i < 4; i++) {
            int row = srow + i * 32;
            cp16(ad + row * LDSD + sc4 * 4, ag + (size_t)row * K + sc4 * 4);
            cp16(bd + row * LDSD + sc4 * 4, bg + (size_t)row * K + sc4 * 4);
        }
    };

    stage(0, 0);
    CP_COMMIT();

    for (int c = 0; c < NC; c++) {
        const int buf = c & 1;
        if (c + 1 < NC) {
            stage(c + 1, buf ^ 1);
            CP_COMMIT();
            CP_WAIT1();
        } else {
            CP_WAIT0();
        }
        __syncthreads();

        const float* As = Asm + buf * TILEF + (wm * 64) * LDSD;
        const float* Bs = Bsm + buf * TILEF + (wn * 32) * LDSD;
#pragma unroll
        for (int kk = 0; kk < 32; kk += 8) {
            uint32_t af[4][4], bf[4][2];
#pragma unroll
            for (int mt = 0; mt < 4; mt++) {
                const float* p = As + (mt * 16 + gl) * LDSD + kk + tg;
                af[mt][0] = __float_as_uint(p[0]);
                af[mt][1] = __float_as_uint(p[8 * LDSD]);
                af[mt][2] = __float_as_uint(p[4]);
                af[mt][3] = __float_as_uint(p[8 * LDSD + 4]);
            }
#pragma unroll
            for (int nt = 0; nt < 4; nt++) {
                const float* p = Bs + (nt * 8 + gl) * LDSD + kk + tg;
                bf[nt][0] = __float_as_uint(p[0]);
                bf[nt][1] = __float_as_uint(p[4]);
            }
#pragma unroll
            for (int mt = 0; mt < 4; mt++)
#pragma unroll
                for (int nt = 0; nt < 4; nt++)
                    mma_tf32(acc[mt][nt], af[mt], bf[nt]);
        }
        __syncthreads();
    }

    // epilogue
#pragma unroll
    for (int mt = 0; mt < 4; mt++) {
        const int r0 = m0 + wm * 64 + mt * 16 + gl;
#pragma unroll
        for (int nt = 0; nt < 4; nt++) {
            const int col = n0 + wn * 32 + nt * 8 + tg * 2;
            const float2 bv = *(const float2*)(bias + col);
            float2 v0, v1;
            v0.x = acc[mt][nt][0] + bv.x;
            v0.y = acc[mt][nt][1] + bv.y;
            v1.x = acc[mt][nt][2] + bv.x;
            v1.y = acc[mt][nt][3] + bv.y;
            if (HAS_SKIP) {
                const float2 s0 = *(const float2*)(skip + (size_t)r0 * N + col);
                const float2 s1 = *(const float2*)(skip + (size_t)(r0 + 8) * N + col);
                v0.x += s0.x; v0.y += s0.y;
                v1.x += s1.x; v1.y += s1.y;
            }
            *(float2*)(C + (size_t)r0 * N + col)       = v0;
            *(float2*)(C + (size_t)(r0 + 8) * N + col) = v1;
        }
    }
}

// ---------------- patch extraction ----------------------------------------
__global__ void patch_kernel(const float* __restrict__ x, float* __restrict__ out) {
    int idx = blockIdx.x * blockDim.x + threadIdx.x;
    if (idx >= BSROWS * EE) return;
    int col = idx % EE;
    int row = idx / EE;
    int b = row / SS, s = row % SS;
    int gy = s / GRID14, gx = s % GRID14;
    int c = col >> 8;
    int r = col & 255;
    int py = r >> 4, px = r & 15;
    out[idx] = x[(((size_t)b * 3 + c) * 224 + (gy * 16 + py)) * 224 + (gx * 16 + px)];
}

// ---------------- LayerNorm over [S,E] per batch ---------------------------
__global__ __launch_bounds__(512)
void ln_reduce(const float* __restrict__ x, float* __restrict__ stats) {
    int b = blockIdx.x;
    const float4* p = (const float4*)(x + (size_t)b * SE);
    float s = 0.f, s2 = 0.f;
    for (int i = threadIdx.x; i < SE / 4; i += blockDim.x) {
        float4 v = p[i];
        s  += v.x + v.y + v.z + v.w;
        s2 += v.x * v.x + v.y * v.y + v.z * v.z + v.w * v.w;
    }
    __shared__ float sh[16], sh2[16];
#pragma unroll
    for (int o = 16; o > 0; o >>= 1) {
        s  += __shfl_xor_sync(0xffffffffu, s, o);
        s2 += __shfl_xor_sync(0xffffffffu, s2, o);
    }
    int w = threadIdx.x >> 5;
    if ((threadIdx.x & 31) == 0) { sh[w] = s; sh2[w] = s2; }
    __syncthreads();
    if (threadIdx.x == 0) {
        float ts = 0.f, ts2 = 0.f;
        for (int i = 0; i < 16; i++) { ts += sh[i]; ts2 += sh2[i]; }
        float mean = ts / (float)SE;
        float var  = ts2 / (float)SE - mean * mean;
        stats[2 * b] = mean;
        stats[2 * b + 1] = rsqrtf(var + LN_EPS);
    }
}

__global__ void ln_apply(const float* __restrict__ x, const float* __restrict__ w,
                         const float* __restrict__ bias, const float* __restrict__ stats,
                         float* __restrict__ out) {
    int idx = blockIdx.x * blockDim.x + threadIdx.x;
    if (idx >= BB * SE) return;
    int b = idx / SE;
    int i = idx - b * SE;
    float mean = stats[2 * b], rstd = stats[2 * b + 1];
    out[idx] = (x[idx] - mean) * rstd * w[i] + bias[i];
}

// ---------------- attention: scores = (Q K^T) / sqrt(HD) -------------------
__global__ __launch_bounds__(256)
void attn_scores(const float* __restrict__ q, const float* __restrict__ k,
                 float* __restrict__ scores) {
    int bh = blockIdx.z;
    int b = bh / HH, h = bh % HH;
    const float* qb = q + (size_t)(b * SS) * EE + h * HD;
    const float* kb = k + (size_t)(b * SS) * EE + h * HD;
    float* sb = scores + (size_t)bh * SS * SS;

    __shared__ float Qs[16][32];
    __shared__ float Ks[16][32];
    int tid = threadIdx.x;
    int tx = tid & 15, ty = tid >> 4;
    int m0 = blockIdx.y * 32, n0 = blockIdx.x * 32;

    float a00 = 0.f, a01 = 0.f, a10 = 0.f, a11 = 0.f;
    int lr = tid >> 4;
    int lc = tid & 15;

    for (int k0 = 0; k0 < HD; k0 += 16) {
#pragma unroll
        for (int j = 0; j < 2; j++) {
            int r = lr + j * 16;
            int m = m0 + r;
            Qs[lc][r] = (m < SS) ? qb[(size_t)m * EE + k0 + lc] : 0.f;
            int n = n0 + r;
            Ks[lc][r] = (n < SS) ? kb[(size_t)n * EE + k0 + lc] : 0.f;
        }
        __syncthreads();
#pragma unroll
        for (int kk = 0; kk < 16; kk++) {
            float q0 = Qs[kk][ty * 2], q1 = Qs[kk][ty * 2 + 1];
            float k0v = Ks[kk][tx * 2], k1v = Ks[kk][tx * 2 + 1];
            a00 += q0 * k0v; a01 += q0 * k1v;
            a10 += q1 * k0v; a11 += q1 * k1v;
        }
        __syncthreads();
    }
    const float scale = 0.07216878364870322f;  // 1/sqrt(192)
    int m = m0 + ty * 2, n = n0 + tx * 2;
    if (m < SS) {
        if (n < SS)     sb[(size_t)m * SS + n]     = a00 * scale;
        if (n + 1 < SS) sb[(size_t)m * SS + n + 1] = a01 * scale;
    }
    if (m + 1 < SS) {
        if (n < SS)     sb[(size_t)(m + 1) * SS + n]     = a10 * scale;
        if (n + 1 < SS) sb[(size_t)(m + 1) * SS + n + 1] = a11 * scale;
    }
}

// ---------------- softmax over rows of scores ------------------------------
__global__ __launch_bounds__(128)
void softmax_k(float* __restrict__ sc) {
    size_t row = blockIdx.x;
    float* p = sc + row * SS;
    int tid = threadIdx.x;
    __shared__ float redm[4], reds[4];

    float mx = -1e30f;
    for (int i = tid; i < SS; i += 128) mx = fmaxf(mx, p[i]);
#pragma unroll
    for (int o = 16; o > 0; o >>= 1) mx = fmaxf(mx, __shfl_xor_sync(0xffffffffu, mx, o));
    if ((tid & 31) == 0) redm[tid >> 5] = mx;
    __syncthreads();
    mx = fmaxf(fmaxf(redm[0], redm[1]), fmaxf(redm[2], redm[3]));

    float sum = 0.f;
    for (int i = tid; i < SS; i += 128) {
        float e = __expf(p[i] - mx);
        p[i] = e;
        sum += e;
    }
#pragma unroll
    for (int o = 16; o > 0; o >>= 1) sum += __shfl_xor_sync(0xffffffffu, sum, o);
    if ((tid & 31) == 0) reds[tid >> 5] = sum;
    __syncthreads();
    sum = reds[0] + reds[1] + reds[2] + reds[3];
    float inv = 1.0f / sum;
    for (int i = tid; i < SS; i += 128) p[i] *= inv;
}

// ---------------- O = attn @ V  (NN gemm, per bh) --------------------------
__global__ __launch_bounds__(256)
void attn_out(const float* __restrict__ attn, const float* __restrict__ v,
              float* __restrict__ o) {
    int bh = blockIdx.z;
    int b = bh / HH, h = bh % HH;
    const float* ab = attn + (size_t)bh * SS * SS;
    const float* vb = v + (size_t)(b * SS) * EE + h * HD;
    float* ob = o + (size_t)(b * SS) * EE + h * HD;

    __shared__ float As[16][32];
    __shared__ float Vs[16][32];
    int tid = threadIdx.x;
    int tx = tid & 15, ty = tid >> 4;
    int m0 = blockIdx.y * 32, n0 = blockIdx.x * 32;

    float a00 = 0.f, a01 = 0.f, a10 = 0.f, a11 = 0.f;
    int lr = tid >> 4, lc = tid & 15;
    int vr = tid >> 5, vc = tid & 31;

    for (int k0 = 0; k0 < SS; k0 += 16) {
#pragma unroll
        for (int j = 0; j < 2; j++) {
            int r = lr + j * 16;
            int m = m0 + r;
            As[lc][r] = (m < SS && (k0 + lc) < SS) ? ab[(size_t)m * SS + k0 + lc] : 0.f;
        }
#pragma unroll
        for (int j = 0; j < 2; j++) {
            int kk = vr + j * 8;
            Vs[kk][vc] = ((k0 + kk) < SS) ? vb[(size_t)(k0 + kk) * EE + n0 + vc] : 0.f;
        }
        __syncthreads();
#pragma unroll
        for (int kk = 0; kk < 16; kk++) {
            float p0 = As[kk][ty * 2], p1 = As[kk][ty * 2 + 1];
            float v0 = Vs[kk][tx * 2], v1 = Vs[kk][tx * 2 + 1];
            a00 += p0 * v0; a01 += p0 * v1;
            a10 += p1 * v0; a11 += p1 * v1;
        }
        __syncthreads();
    }
    int m = m0 + ty * 2, n = n0 + tx * 2;
    if (m < SS) {
        ob[(size_t)m * EE + n]     = a00;
        ob[(size_t)m * EE + n + 1] = a01;
    }
    if (m + 1 < SS) {
        ob[(size_t)(m + 1) * EE + n]     = a10;
        ob[(size_t)(m + 1) * EE + n + 1] = a11;
    }
}

// ---------------- launch ----------------------------------------------------
extern "C" void kernel_launch(void* const* d_in, const int* in_sizes, int n_in,
                              void* d_out, int out_size) {
    const float* x      = (const float*)d_in[0];
    const float* conv_w = (const float*)d_in[1];
    const float* conv_b = (const float*)d_in[2];
    const float* wq     = (const float*)d_in[3];
    const float* bq     = (const float*)d_in[4];
    const float* wk     = (const float*)d_in[5];
    const float* bk     = (const float*)d_in[6];
    const float* wv     = (const float*)d_in[7];
    const float* bv     = (const float*)d_in[8];
    const float* wo     = (const float*)d_in[9];
    const float* bo     = (const float*)d_in[10];
    const float* ln1w   = (const float*)d_in[11];
    const float* ln1b   = (const float*)d_in[12];
    const float* ln2w   = (const float*)d_in[13];
    const float* ln2b   = (const float*)d_in[14];
    float* out = (float*)d_out;

    float *patches, *emb, *h, *q, *k, *v, *sc, *ao, *res, *stats;
    cudaGetSymbolAddress((void**)&patches, g_patches);
    cudaGetSymbolAddress((void**)&emb,     g_emb);
    cudaGetSymbolAddress((void**)&h,       g_h);
    cudaGetSymbolAddress((void**)&q,       g_q);
    cudaGetSymbolAddress((void**)&k,       g_k);
    cudaGetSymbolAddress((void**)&v,       g_v);
    cudaGetSymbolAddress((void**)&sc,      g_scores);
    cudaGetSymbolAddress((void**)&ao,      g_attno);
    cudaGetSymbolAddress((void**)&res,     g_res);
    cudaGetSymbolAddress((void**)&stats,   g_stats);

    cudaFuncSetAttribute(gemm_mma<false>,
                         cudaFuncAttributeMaxDynamicSharedMemorySize, GEMM_SMEM_BYTES);
    cudaFuncSetAttribute(gemm_mma<true>,
                         cudaFuncAttributeMaxDynamicSharedMemorySize, GEMM_SMEM_BYTES);

    dim3 tc_grid(EE / 128, BSROWS / 128);   // (6, 98)

    // 1. patch extraction
    patch_kernel<<<(BSROWS * EE + 255) / 256, 256>>>(x, patches);
    // 2. patch embedding GEMM (tf32 mma)
    gemm_mma<false><<<tc_grid, 256, GEMM_SMEM_BYTES>>>(patches, conv_w, conv_b,
                                                       nullptr, emb, BSROWS, EE, EE);
    // 3. LN1
    ln_reduce<<<BB, 512>>>(emb, stats);
    ln_apply<<<(BB * SE + 255) / 256, 256>>>(emb, ln1w, ln1b, stats, h);
    // 4. QKV (tf32 mma)
    gemm_mma<false><<<tc_grid, 256, GEMM_SMEM_BYTES>>>(h, wq, bq, nullptr, q, BSROWS, EE, EE);
    gemm_mma<false><<<tc_grid, 256, GEMM_SMEM_BYTES>>>(h, wk, bk, nullptr, k, BSROWS, EE, EE);
    gemm_mma<false><<<tc_grid, 256, GEMM_SMEM_BYTES>>>(h, wv, bv, nullptr, v, BSROWS, EE, EE);
    // 5. attention
    attn_scores<<<dim3(7, 7, BB * HH), 256>>>(q, k, sc);
    softmax_k<<<BB * HH * SS, 128>>>(sc);
    attn_out<<<dim3(HD / 32, 7, BB * HH), 256>>>(sc, v, ao);
    // 6. output projection + residual (tf32 mma)
    gemm_mma<true><<<tc_grid, 256, GEMM_SMEM_BYTES>>>(ao, wo, bo, emb, res, BSROWS, EE, EE);
    // 7. LN2 -> d_out
    ln_reduce<<<BB, 512>>>(res, stats);
    ln_apply<<<(BB * SE + 255) / 256, 256>>>(res, ln2w, ln2b, stats, out);
}

// round 6
// speedup vs baseline: 7.3508x; 1.9809x over previous
#include <cuda_runtime.h>
#include <math.h>
#include <stdint.h>

#define BB 64
#define SS 196
#define EE 768
#define HH 4
#define HD 192
#define SP 224              /* padded seq (196 -> 224 = 7*32) */
#define GRID14 14
#define BSROWS (BB*SS)      /* 12544 */
#define SE (SS*EE)          /* 150528 */
#define LN_EPS 1e-5f

// ---------------- scratch (static device arrays; no cudaMalloc) -------------
__device__ float g_patches[BSROWS*EE];
__device__ float g_emb[BSROWS*EE];      // skip1
__device__ float g_h[BSROWS*EE];        // LN1 output
__device__ float g_q[BSROWS*EE];
__device__ float g_k[BSROWS*EE];
__device__ float g_v[BSROWS*EE];
__device__ float g_vt[BB*HH*HD*SP];     // V transposed per head, s padded
__device__ float g_scores[BB*HH*SP*SP]; // padded scores/probs
__device__ float g_attno[BSROWS*EE];
__device__ float g_res[BSROWS*EE];      // skip1 + proj (pre-LN2)
__device__ float g_stats[BB*2];         // mean, rstd per batch

// =================== helpers ================================================
__device__ __forceinline__ uint32_t smem_u32(const void* p) {
    uint32_t a;
    asm("{ .reg .u64 t; cvta.to.shared.u64 t, %1; cvt.u32.u64 %0, t; }"
        : "=r"(a) : "l"(p));
    return a;
}

__device__ __forceinline__ void cp16(void* smem_dst, const void* gmem_src) {
    uint32_t s = smem_u32(smem_dst);
    asm volatile("cp.async.cg.shared.global [%0], [%1], 16;"
                 :: "r"(s), "l"(gmem_src) : "memory");
}
// zero-fill variant: src-size 0 copies nothing, fills 16B with zeros
__device__ __forceinline__ void cp16z(void* smem_dst, const void* gmem_src, bool v) {
    uint32_t s = smem_u32(smem_dst);
    int sz = v ? 16 : 0;
    asm volatile("cp.async.cg.shared.global [%0], [%1], 16, %2;"
                 :: "r"(s), "l"(gmem_src), "r"(sz) : "memory");
}
#define CP_COMMIT() asm volatile("cp.async.commit_group;" ::: "memory")
#define CP_WAIT0()  asm volatile("cp.async.wait_group 0;" ::: "memory")
#define CP_WAIT1()  asm volatile("cp.async.wait_group 1;" ::: "memory")

// mma.sync m16n8k8 tf32: D(16x8,f32) += A(16x8,tf32) * B(8x8,tf32)
__device__ __forceinline__ void mma_tf32(float* c, const uint32_t* a,
                                         const uint32_t* b) {
    asm volatile(
        "mma.sync.aligned.m16n8k8.row.col.f32.tf32.tf32.f32 "
        "{%0,%1,%2,%3}, {%4,%5,%6,%7}, {%8,%9}, {%0,%1,%2,%3};"
        : "+f"(c[0]), "+f"(c[1]), "+f"(c[2]), "+f"(c[3])
        : "r"(a[0]), "r"(a[1]), "r"(a[2]), "r"(a[3]), "r"(b[0]), "r"(b[1]));
}

// =================== tile framework constants ===============================
#define LDSD 36                       /* padded row stride (floats) */
#define TILEF (128 * LDSD)            /* floats per (A or B) buffer */
#define GEMM_SMEM_BYTES (4 * TILEF * 4)   /* 73728 B */

// inner compute over one staged 128x32 x 128x32 chunk pair
#define MMA_CHUNK_COMPUTE(As, Bs)                                             \
    do {                                                                      \
        _Pragma("unroll")                                                     \
        for (int kk = 0; kk < 32; kk += 8) {                                  \
            uint32_t af[4][4], bf[4][2];                                      \
            _Pragma("unroll")                                                 \
            for (int mt = 0; mt < 4; mt++) {                                  \
                const float* p = (As) + (mt * 16 + gl) * LDSD + kk + tg;      \
                af[mt][0] = __float_as_uint(p[0]);                            \
                af[mt][1] = __float_as_uint(p[8 * LDSD]);                     \
                af[mt][2] = __float_as_uint(p[4]);                            \
                af[mt][3] = __float_as_uint(p[8 * LDSD + 4]);                 \
            }                                                                 \
            _Pragma("unroll")                                                 \
            for (int nt = 0; nt < 4; nt++) {                                  \
                const float* p = (Bs) + (nt * 8 + gl) * LDSD + kk + tg;       \
                bf[nt][0] = __float_as_uint(p[0]);                            \
                bf[nt][1] = __float_as_uint(p[4]);                            \
            }                                                                 \
            _Pragma("unroll")                                                 \
            for (int mt = 0; mt < 4; mt++)                                    \
                _Pragma("unroll")                                             \
                for (int nt = 0; nt < 4; nt++)                                \
                    mma_tf32(acc[mt][nt], af[mt], bf[nt]);                    \
        }                                                                     \
    } while (0)

// =================== tf32 GEMM: C = A * B^T + bias (+skip) ==================
// CTA tile 128x128, BK=32, 256 threads. M%128==0, N%128==0, K%32==0.
template <bool HAS_SKIP>
__global__ __launch_bounds__(256)
void gemm_mma(const float* __restrict__ A, const float* __restrict__ Bm,
              const float* __restrict__ bias, const float* __restrict__ skip,
              float* __restrict__ C, int M, int N, int K) {
    extern __shared__ float sm[];
    float* Asm = sm;
    float* Bsm = sm + 2 * TILEF;

    const int tid = threadIdx.x;
    const int wid = tid >> 5, lane = tid & 31;
    const int wm = wid >> 2, wn = wid & 3;
    const int gl = lane >> 2, tg = lane & 3;

    const int m0 = blockIdx.y * 128, n0 = blockIdx.x * 128;
    const float* Ab = A + (size_t)m0 * K;
    const float* Bb = Bm + (size_t)n0 * K;

    const int srow = tid >> 3;
    const int sc4  = tid & 7;

    float acc[4][4][4];
#pragma unroll
    for (int i = 0; i < 4; i++)
#pragma unroll
        for (int j = 0; j < 4; j++)
#pragma unroll
            for (int r = 0; r < 4; r++) acc[i][j][r] = 0.f;

    const int NC = K >> 5;

    auto stage = [&](int c, int buf) {
        const float* ag = Ab + c * 32;
        const float* bg = Bb + c * 32;
        float* ad = Asm + buf * TILEF;
        float* bd = Bsm + buf * TILEF;
#pragma unroll
        for (int i = 0; i < 4; i++) {
            int row = srow + i * 32;
            cp16(ad + row * LDSD + sc4 * 4, ag + (size_t)row * K + sc4 * 4);
            cp16(bd + row * LDSD + sc4 * 4, bg + (size_t)row * K + sc4 * 4);
        }
    };

    stage(0, 0);
    CP_COMMIT();

    for (int c = 0; c < NC; c++) {
        const int buf = c & 1;
        if (c + 1 < NC) {
            stage(c + 1, buf ^ 1);
            CP_COMMIT();
            CP_WAIT1();
        } else {
            CP_WAIT0();
        }
        __syncthreads();
        const float* As = Asm + buf * TILEF + (wm * 64) * LDSD;
        const float* Bs = Bsm + buf * TILEF + (wn * 32) * LDSD;
        MMA_CHUNK_COMPUTE(As, Bs);
        __syncthreads();
    }

#pragma unroll
    for (int mt = 0; mt < 4; mt++) {
        const int r0 = m0 + wm * 64 + mt * 16 + gl;
#pragma unroll
        for (int nt = 0; nt < 4; nt++) {
            const int col = n0 + wn * 32 + nt * 8 + tg * 2;
            const float2 bv = *(const float2*)(bias + col);
            float2 v0, v1;
            v0.x = acc[mt][nt][0] + bv.x;
            v0.y = acc[mt][nt][1] + bv.y;
            v1.x = acc[mt][nt][2] + bv.x;
            v1.y = acc[mt][nt][3] + bv.y;
            if (HAS_SKIP) {
                const float2 s0 = *(const float2*)(skip + (size_t)r0 * N + col);
                const float2 s1 = *(const float2*)(skip + (size_t)(r0 + 8) * N + col);
                v0.x += s0.x; v0.y += s0.y;
                v1.x += s1.x; v1.y += s1.y;
            }
            *(float2*)(C + (size_t)r0 * N + col)       = v0;
            *(float2*)(C + (size_t)(r0 + 8) * N + col) = v1;
        }
    }
}

// =================== attention scores: S = Q K^T / sqrt(HD), tf32 mma =======
// grid (2, 2, B*H); M=N=196 guarded inside 128-tiles; K=HD=192.
__global__ __launch_bounds__(256)
void scores_mma(const float* __restrict__ q, const float* __restrict__ k,
                float* __restrict__ sc) {
    extern __shared__ float sm[];
    float* Asm = sm;
    float* Bsm = sm + 2 * TILEF;

    const int tid = threadIdx.x;
    const int wid = tid >> 5, lane = tid & 31;
    const int wm = wid >> 2, wn = wid & 3;
    const int gl = lane >> 2, tg = lane & 3;

    const int bh = blockIdx.z;
    const int b = bh >> 2, h = bh & 3;
    const int m0 = blockIdx.y * 128, n0 = blockIdx.x * 128;
    const int avalid = SS - m0;          // rows of Q valid in this tile
    const int bvalid = SS - n0;          // rows of K valid

    const float* qb = q + (size_t)(b * SS) * EE + h * HD;
    const float* kb = k + (size_t)(b * SS) * EE + h * HD;
    float* cb = sc + (size_t)bh * SP * SP;

    const int srow = tid >> 3;
    const int sc4  = tid & 7;

    float acc[4][4][4];
#pragma unroll
    for (int i = 0; i < 4; i++)
#pragma unroll
        for (int j = 0; j < 4; j++)
#pragma unroll
            for (int r = 0; r < 4; r++) acc[i][j][r] = 0.f;

    const int NC = HD >> 5;   // 6

    auto stage = [&](int c, int buf) {
        float* ad = Asm + buf * TILEF;
        float* bd = Bsm + buf * TILEF;
#pragma unroll
        for (int i = 0; i < 4; i++) {
            int row = srow + i * 32;
            bool va = row < avalid, vb = row < bvalid;
            int ra = va ? (m0 + row) : 0;
            int rb = vb ? (n0 + row) : 0;
            cp16z(ad + row * LDSD + sc4 * 4, qb + (size_t)ra * EE + c * 32 + sc4 * 4, va);
            cp16z(bd + row * LDSD + sc4 * 4, kb + (size_t)rb * EE + c * 32 + sc4 * 4, vb);
        }
    };

    stage(0, 0);
    CP_COMMIT();
    for (int c = 0; c < NC; c++) {
        const int buf = c & 1;
        if (c + 1 < NC) { stage(c + 1, buf ^ 1); CP_COMMIT(); CP_WAIT1(); }
        else           { CP_WAIT0(); }
        __syncthreads();
        const float* As = Asm + buf * TILEF + (wm * 64) * LDSD;
        const float* Bs = Bsm + buf * TILEF + (wn * 32) * LDSD;
        MMA_CHUNK_COMPUTE(As, Bs);
        __syncthreads();
    }

    const float scale = 0.07216878364870322f;  // 1/sqrt(192)
#pragma unroll
    for (int mt = 0; mt < 4; mt++) {
        const int r0 = m0 + wm * 64 + mt * 16 + gl;
#pragma unroll
        for (int nt = 0; nt < 4; nt++) {
            const int col = n0 + wn * 32 + nt * 8 + tg * 2;
            if (col < SS) {
                if (r0 < SS) {
                    float2 v; v.x = acc[mt][nt][0] * scale; v.y = acc[mt][nt][1] * scale;
                    *(float2*)(cb + (size_t)r0 * SP + col) = v;
                }
                if (r0 + 8 < SS) {
                    float2 v; v.x = acc[mt][nt][2] * scale; v.y = acc[mt][nt][3] * scale;
                    *(float2*)(cb + (size_t)(r0 + 8) * SP + col) = v;
                }
            }
        }
    }
}

// =================== attention output: O = P @ V, tf32 mma ==================
// A = P [196, 224] (lda=SP), B = Vt [192, 224] (ldb=SP), K=224.
// grid (2, 2, B*H): x = n-tile over HD (128+64), y = m-tile over S.
__global__ __launch_bounds__(256)
void attnout_mma(const float* __restrict__ sc, const float* __restrict__ vt,
                 float* __restrict__ o) {
    extern __shared__ float sm[];
    float* Asm = sm;
    float* Bsm = sm + 2 * TILEF;

    const int tid = threadIdx.x;
    const int wid = tid >> 5, lane = tid & 31;
    const int wm = wid >> 2, wn = wid & 3;
    const int gl = lane >> 2, tg = lane & 3;

    const int bh = blockIdx.z;
    const int b = bh >> 2, h = bh & 3;
    const int m0 = blockIdx.y * 128, n0 = blockIdx.x * 128;
    const int avalid = SS - m0;
    const int bvalid = HD - n0;          // 128 or 64

    const float* Ab = sc + (size_t)bh * SP * SP;
    const float* Bb = vt + (size_t)bh * HD * SP;
    float* ob = o + (size_t)(b * SS) * EE + h * HD;

    const int srow = tid >> 3;
    const int sc4  = tid & 7;

    float acc[4][4][4];
#pragma unroll
    for (int i = 0; i < 4; i++)
#pragma unroll
        for (int j = 0; j < 4; j++)
#pragma unroll
            for (int r = 0; r < 4; r++) acc[i][j][r] = 0.f;

    const int NC = SP >> 5;   // 7

    auto stage = [&](int c, int buf) {
        float* ad = Asm + buf * TILEF;
        float* bd = Bsm + buf * TILEF;
#pragma unroll
        for (int i = 0; i < 4; i++) {
            int row = srow + i * 32;
            bool va = row < avalid, vb = row < bvalid;
            int ra = va ? (m0 + row) : 0;
            int rb = vb ? (n0 + row) : 0;
            cp16z(ad + row * LDSD + sc4 * 4, Ab + (size_t)ra * SP + c * 32 + sc4 * 4, va);
            cp16z(bd + row * LDSD + sc4 * 4, Bb + (size_t)rb * SP + c * 32 + sc4 * 4, vb);
        }
    };

    stage(0, 0);
    CP_COMMIT();
    for (int c = 0; c < NC; c++) {
        const int buf = c & 1;
        if (c + 1 < NC) { stage(c + 1, buf ^ 1); CP_COMMIT(); CP_WAIT1(); }
        else           { CP_WAIT0(); }
        __syncthreads();
        const float* As = Asm + buf * TILEF + (wm * 64) * LDSD;
        const float* Bs = Bsm + buf * TILEF + (wn * 32) * LDSD;
        MMA_CHUNK_COMPUTE(As, Bs);
        __syncthreads();
    }

#pragma unroll
    for (int mt = 0; mt < 4; mt++) {
        const int r0 = m0 + wm * 64 + mt * 16 + gl;
#pragma unroll
        for (int nt = 0; nt < 4; nt++) {
            const int col = n0 + wn * 32 + nt * 8 + tg * 2;
            if (col < HD) {
                if (r0 < SS) {
                    float2 v; v.x = acc[mt][nt][0]; v.y = acc[mt][nt][1];
                    *(float2*)(ob + (size_t)r0 * EE + col) = v;
                }
                if (r0 + 8 < SS) {
                    float2 v; v.x = acc[mt][nt][2]; v.y = acc[mt][nt][3];
                    *(float2*)(ob + (size_t)(r0 + 8) * EE + col) = v;
                }
            }
        }
    }
}

// ---------------- V transpose: v[b,s,h,d] -> vt[bh][d][s padded] ------------
__global__ __launch_bounds__(256)
void vt_kernel(const float* __restrict__ v, float* __restrict__ vt) {
    __shared__ float t[32][33];
    const int bh = blockIdx.z;
    const int b = bh >> 2, h = bh & 3;
    const int s0 = blockIdx.x * 32, d0 = blockIdx.y * 32;
    const int tx = threadIdx.x & 31, ty = threadIdx.x >> 5;  // 32x8

    for (int i = ty; i < 32; i += 8) {
        int s = s0 + i, d = d0 + tx;
        float val = (s < SS) ? v[(size_t)(b * SS + s) * EE + h * HD + d] : 0.f;
        t[tx][i] = val;     // t[d-local][s-local]
    }
    __syncthreads();
    for (int i = ty; i < 32; i += 8) {
        int d = d0 + i, s = s0 + tx;
        vt[((size_t)bh * HD + d) * SP + s] = t[i][tx];
    }
}

// ---------------- patch extraction ----------------------------------------
__global__ void patch_kernel(const float* __restrict__ x, float* __restrict__ out) {
    int idx = blockIdx.x * blockDim.x + threadIdx.x;
    if (idx >= BSROWS * EE) return;
    int col = idx % EE;
    int row = idx / EE;
    int b = row / SS, s = row % SS;
    int gy = s / GRID14, gx = s % GRID14;
    int c = col >> 8;
    int r = col & 255;
    int py = r >> 4, px = r & 15;
    out[idx] = x[(((size_t)b * 3 + c) * 224 + (gy * 16 + py)) * 224 + (gx * 16 + px)];
}

// ---------------- LayerNorm over [S,E] per batch ---------------------------
__global__ __launch_bounds__(512)
void ln_reduce(const float* __restrict__ x, float* __restrict__ stats) {
    int b = blockIdx.x;
    const float4* p = (const float4*)(x + (size_t)b * SE);
    float s = 0.f, s2 = 0.f;
    for (int i = threadIdx.x; i < SE / 4; i += blockDim.x) {
        float4 v = p[i];
        s  += v.x + v.y + v.z + v.w;
        s2 += v.x * v.x + v.y * v.y + v.z * v.z + v.w * v.w;
    }
    __shared__ float sh[16], sh2[16];
#pragma unroll
    for (int o = 16; o > 0; o >>= 1) {
        s  += __shfl_xor_sync(0xffffffffu, s, o);
        s2 += __shfl_xor_sync(0xffffffffu, s2, o);
    }
    int w = threadIdx.x >> 5;
    if ((threadIdx.x & 31) == 0) { sh[w] = s; sh2[w] = s2; }
    __syncthreads();
    if (threadIdx.x == 0) {
        float ts = 0.f, ts2 = 0.f;
        for (int i = 0; i < 16; i++) { ts += sh[i]; ts2 += sh2[i]; }
        float mean = ts / (float)SE;
        float var  = ts2 / (float)SE - mean * mean;
        stats[2 * b] = mean;
        stats[2 * b + 1] = rsqrtf(var + LN_EPS);
    }
}

__global__ void ln_apply(const float* __restrict__ x, const float* __restrict__ w,
                         const float* __restrict__ bias, const float* __restrict__ stats,
                         float* __restrict__ out) {
    int idx = blockIdx.x * blockDim.x + threadIdx.x;
    if (idx >= BB * SE) return;
    int b = idx / SE;
    int i = idx - b * SE;
    float mean = stats[2 * b], rstd = stats[2 * b + 1];
    out[idx] = (x[idx] - mean) * rstd * w[i] + bias[i];
}

// ---------------- softmax over rows of padded scores -----------------------
// grid (196, B*H), block 128. Also zeroes padding columns [196,224).
__global__ __launch_bounds__(128)
void softmax_k(float* __restrict__ sc) {
    const int bh = blockIdx.y;
    float* p = sc + (size_t)bh * SP * SP + (size_t)blockIdx.x * SP;
    int tid = threadIdx.x;
    __shared__ float redm[4], reds[4];

    float mx = -1e30f;
    for (int i = tid; i < SS; i += 128) mx = fmaxf(mx, p[i]);
#pragma unroll
    for (int o = 16; o > 0; o >>= 1) mx = fmaxf(mx, __shfl_xor_sync(0xffffffffu, mx, o));
    if ((tid & 31) == 0) redm[tid >> 5] = mx;
    __syncthreads();
    mx = fmaxf(fmaxf(redm[0], redm[1]), fmaxf(redm[2], redm[3]));

    float sum = 0.f;
    for (int i = tid; i < SS; i += 128) {
        float e = __expf(p[i] - mx);
        p[i] = e;
        sum += e;
    }
#pragma unroll
    for (int o = 16; o > 0; o >>= 1) sum += __shfl_xor_sync(0xffffffffu, sum, o);
    if ((tid & 31) == 0) reds[tid >> 5] = sum;
    __syncthreads();
    sum = reds[0] + reds[1] + reds[2] + reds[3];
    float inv = 1.0f / sum;
    for (int i = tid; i < SP; i += 128)
        p[i] = (i < SS) ? p[i] * inv : 0.f;
}

// ---------------- launch ----------------------------------------------------
extern "C" void kernel_launch(void* const* d_in, const int* in_sizes, int n_in,
                              void* d_out, int out_size) {
    const float* x      = (const float*)d_in[0];
    const float* conv_w = (const float*)d_in[1];
    const float* conv_b = (const float*)d_in[2];
    const float* wq     = (const float*)d_in[3];
    const float* bq     = (const float*)d_in[4];
    const float* wk     = (const float*)d_in[5];
    const float* bk     = (const float*)d_in[6];
    const float* wv     = (const float*)d_in[7];
    const float* bv     = (const float*)d_in[8];
    const float* wo     = (const float*)d_in[9];
    const float* bo     = (const float*)d_in[10];
    const float* ln1w   = (const float*)d_in[11];
    const float* ln1b   = (const float*)d_in[12];
    const float* ln2w   = (const float*)d_in[13];
    const float* ln2b   = (const float*)d_in[14];
    float* out = (float*)d_out;

    float *patches, *emb, *h, *q, *k, *v, *vt, *sc, *ao, *res, *stats;
    cudaGetSymbolAddress((void**)&patches, g_patches);
    cudaGetSymbolAddress((void**)&emb,     g_emb);
    cudaGetSymbolAddress((void**)&h,       g_h);
    cudaGetSymbolAddress((void**)&q,       g_q);
    cudaGetSymbolAddress((void**)&k,       g_k);
    cudaGetSymbolAddress((void**)&v,       g_v);
    cudaGetSymbolAddress((void**)&vt,      g_vt);
    cudaGetSymbolAddress((void**)&sc,      g_scores);
    cudaGetSymbolAddress((void**)&ao,      g_attno);
    cudaGetSymbolAddress((void**)&res,     g_res);
    cudaGetSymbolAddress((void**)&stats,   g_stats);

    cudaFuncSetAttribute(gemm_mma<false>,
                         cudaFuncAttributeMaxDynamicSharedMemorySize, GEMM_SMEM_BYTES);
    cudaFuncSetAttribute(gemm_mma<true>,
                         cudaFuncAttributeMaxDynamicSharedMemorySize, GEMM_SMEM_BYTES);
    cudaFuncSetAttribute(scores_mma,
                         cudaFuncAttributeMaxDynamicSharedMemorySize, GEMM_SMEM_BYTES);
    cudaFuncSetAttribute(attnout_mma,
                         cudaFuncAttributeMaxDynamicSharedMemorySize, GEMM_SMEM_BYTES);

    dim3 tc_grid(EE / 128, BSROWS / 128);   // (6, 98)

    // 1. patch extraction
    patch_kernel<<<(BSROWS * EE + 255) / 256, 256>>>(x, patches);
    // 2. patch embedding GEMM
    gemm_mma<false><<<tc_grid, 256, GEMM_SMEM_BYTES>>>(patches, conv_w, conv_b,
                                                       nullptr, emb, BSROWS, EE, EE);
    // 3. LN1
    ln_reduce<<<BB, 512>>>(emb, stats);
    ln_apply<<<(BB * SE + 255) / 256, 256>>>(emb, ln1w, ln1b, stats, h);
    // 4. QKV
    gemm_mma<false><<<tc_grid, 256, GEMM_SMEM_BYTES>>>(h, wq, bq, nullptr, q, BSROWS, EE, EE);
    gemm_mma<false><<<tc_grid, 256, GEMM_SMEM_BYTES>>>(h, wk, bk, nullptr, k, BSROWS, EE, EE);
    gemm_mma<false><<<tc_grid, 256, GEMM_SMEM_BYTES>>>(h, wv, bv, nullptr, v, BSROWS, EE, EE);
    // 5. attention (tensor cores)
    vt_kernel<<<dim3(SP / 32, HD / 32, BB * HH), 256>>>(v, vt);
    scores_mma<<<dim3(2, 2, BB * HH), 256, GEMM_SMEM_BYTES>>>(q, k, sc);
    softmax_k<<<dim3(SS, BB * HH), 128>>>(sc);
    attnout_mma<<<dim3(2, 2, BB * HH), 256, GEMM_SMEM_BYTES>>>(sc, vt, ao);
    // 6. output projection + residual
    gemm_mma<true><<<tc_grid, 256, GEMM_SMEM_BYTES>>>(ao, wo, bo, emb, res, BSROWS, EE, EE);
    // 7. LN2 -> d_out
    ln_reduce<<<BB, 512>>>(res, stats);
    ln_apply<<<(BB * SE + 255) / 256, 256>>>(res, ln2w, ln2b, stats, out);
}

// round 8
// speedup vs baseline: 7.8680x; 1.0704x over previous
#include <cuda_runtime.h>
#include <math.h>
#include <stdint.h>

#define BB 64
#define SS 196
#define EE 768
#define HH 4
#define HD 192
#define SP 224              /* padded seq (196 -> 224 = 7*32) */
#define GRID14 14
#define BSROWS (BB*SS)      /* 12544 */
#define SE (SS*EE)          /* 150528 */
#define LN_EPS 1e-5f

// ---------------- scratch (static device arrays; no cudaMalloc) -------------
__device__ float g_emb[BSROWS*EE];      // skip1
__device__ float g_h[BSROWS*EE];        // LN1 output
__device__ float g_q[BSROWS*EE];
__device__ float g_k[BSROWS*EE];
__device__ float g_v[BSROWS*EE];
__device__ float g_vt[BB*HH*HD*SP];     // V transposed per head, s padded
__device__ float g_scores[BB*HH*SP*SP]; // padded scores/probs
__device__ float g_attno[BSROWS*EE];
__device__ float g_res[BSROWS*EE];      // skip1 + proj (pre-LN2)
__device__ float g_stats[BB*2];         // mean, rstd per batch

// =================== helpers ================================================
__device__ __forceinline__ uint32_t smem_u32(const void* p) {
    uint32_t a;
    asm("{ .reg .u64 t; cvta.to.shared.u64 t, %1; cvt.u32.u64 %0, t; }"
        : "=r"(a) : "l"(p));
    return a;
}

__device__ __forceinline__ void cp16(void* smem_dst, const void* gmem_src) {
    uint32_t s = smem_u32(smem_dst);
    asm volatile("cp.async.cg.shared.global [%0], [%1], 16;"
                 :: "r"(s), "l"(gmem_src) : "memory");
}
__device__ __forceinline__ void cp16z(void* smem_dst, const void* gmem_src, bool v) {
    uint32_t s = smem_u32(smem_dst);
    int sz = v ? 16 : 0;
    asm volatile("cp.async.cg.shared.global [%0], [%1], 16, %2;"
                 :: "r"(s), "l"(gmem_src), "r"(sz) : "memory");
}
#define CP_COMMIT() asm volatile("cp.async.commit_group;" ::: "memory")
#define CP_WAIT0()  asm volatile("cp.async.wait_group 0;" ::: "memory")
#define CP_WAIT1()  asm volatile("cp.async.wait_group 1;" ::: "memory")

// mma.sync m16n8k8 tf32: D(16x8,f32) += A(16x8,tf32) * B(8x8,tf32)
__device__ __forceinline__ void mma_tf32(float* c, const uint32_t* a,
                                         const uint32_t* b) {
    asm volatile(
        "mma.sync.aligned.m16n8k8.row.col.f32.tf32.tf32.f32 "
        "{%0,%1,%2,%3}, {%4,%5,%6,%7}, {%8,%9}, {%0,%1,%2,%3};"
        : "+f"(c[0]), "+f"(c[1]), "+f"(c[2]), "+f"(c[3])
        : "r"(a[0]), "r"(a[1]), "r"(a[2]), "r"(a[3]), "r"(b[0]), "r"(b[1]));
}

// =================== tile framework constants ===============================
#define LDSD 36                       /* padded row stride (floats) */
#define TILEF (128 * LDSD)            /* floats per (A or B) buffer */
#define GEMM2_SMEM_BYTES (4 * TILEF * 4)   /* 73728 B (2-stage, attention) */
#define GEMM3_SMEM_BYTES (6 * TILEF * 4)   /* 110592 B (3-stage, big GEMMs) */

#define MMA_CHUNK_COMPUTE(As, Bs)                                             \
    do {                                                                      \
        _Pragma("unroll")                                                     \
        for (int kk = 0; kk < 32; kk += 8) {                                  \
            uint32_t af[4][4], bf[4][2];                                      \
            _Pragma("unroll")                                                 \
            for (int mt = 0; mt < 4; mt++) {                                  \
                const float* p = (As) + (mt * 16 + gl) * LDSD + kk + tg;      \
                af[mt][0] = __float_as_uint(p[0]);                            \
                af[mt][1] = __float_as_uint(p[8 * LDSD]);                     \
                af[mt][2] = __float_as_uint(p[4]);                            \
                af[mt][3] = __float_as_uint(p[8 * LDSD + 4]);                 \
            }                                                                 \
            _Pragma("unroll")                                                 \
            for (int nt = 0; nt < 4; nt++) {                                  \
                const float* p = (Bs) + (nt * 8 + gl) * LDSD + kk + tg;       \
                bf[nt][0] = __float_as_uint(p[0]);                            \
                bf[nt][1] = __float_as_uint(p[4]);                            \
            }                                                                 \
            _Pragma("unroll")                                                 \
            for (int mt = 0; mt < 4; mt++)                                    \
                _Pragma("unroll")                                             \
                for (int nt = 0; nt < 4; nt++)                                \
                    mma_tf32(acc[mt][nt], af[mt], bf[nt]);                    \
        }                                                                     \
    } while (0)

// patch-gather address: row m of the virtual patch matrix, column col
__device__ __forceinline__ const float* embed_addr(const float* x, int m, int col) {
    int b = m / SS, s = m - b * SS;
    int gy = s / GRID14, gx = s - gy * GRID14;
    int ch = col >> 8, r = col & 255;
    int py = r >> 4, px = r & 15;
    return x + (((size_t)(b * 3 + ch) * 224 + (gy * 16 + py)) * 224 + gx * 16 + px);
}

// =================== 3-stage tf32 GEMM body =================================
// C[M,N] = A[M,K]*B[N,K]^T + bias (+skip). M%128==0, N%128==0, K%32==0.
// MODE 0: A from gmem row-major.  MODE 1: A = patch-gather from image x.
template <int MODE, bool HAS_SKIP>
__device__ __forceinline__ void gemm3_body(
    float* sm, const float* __restrict__ A, const float* __restrict__ Bm,
    const float* __restrict__ bias, const float* __restrict__ skip,
    float* __restrict__ C, int M, int N, int K, int m0, int n0) {
    const int tid = threadIdx.x;
    const int wid = tid >> 5, lane = tid & 31;
    const int wm = wid >> 2, wn = wid & 3;
    const int gl = lane >> 2, tg = lane & 3;
    const int srow = tid >> 3, sc4 = tid & 7;

    float acc[4][4][4];
#pragma unroll
    for (int i = 0; i < 4; i++)
#pragma unroll
        for (int j = 0; j < 4; j++)
#pragma unroll
            for (int r = 0; r < 4; r++) acc[i][j][r] = 0.f;

    const int NC = K >> 5;

    auto stage = [&](int c, int buf) {
        float* ad = sm + buf * (2 * TILEF);
        float* bd = ad + TILEF;
        const int colbase = c * 32 + sc4 * 4;
#pragma unroll
        for (int i = 0; i < 4; i++) {
            int row = srow + i * 32;
            const float* asrc;
            if (MODE == 1) asrc = embed_addr(A, m0 + row, colbase);
            else           asrc = A + (size_t)(m0 + row) * K + colbase;
            cp16(ad + row * LDSD + sc4 * 4, asrc);
            cp16(bd + row * LDSD + sc4 * 4, Bm + (size_t)(n0 + row) * K + colbase);
        }
    };

    stage(0, 0); CP_COMMIT();
    stage(1, 1); CP_COMMIT();

    for (int c = 0; c < NC; c++) {
        if (c + 1 < NC) CP_WAIT1(); else CP_WAIT0();
        __syncthreads();
        if (c + 2 < NC) { stage(c + 2, (c + 2) % 3); CP_COMMIT(); }
        const int buf = c % 3;
        const float* As = sm + buf * (2 * TILEF) + (wm * 64) * LDSD;
        const float* Bs = sm + buf * (2 * TILEF) + TILEF + (wn * 32) * LDSD;
        MMA_CHUNK_COMPUTE(As, Bs);
    }

#pragma unroll
    for (int mt = 0; mt < 4; mt++) {
        const int r0 = m0 + wm * 64 + mt * 16 + gl;
#pragma unroll
        for (int nt = 0; nt < 4; nt++) {
            const int col = n0 + wn * 32 + nt * 8 + tg * 2;
            const float2 bv = *(const float2*)(bias + col);
            float2 v0, v1;
            v0.x = acc[mt][nt][0] + bv.x;
            v0.y = acc[mt][nt][1] + bv.y;
            v1.x = acc[mt][nt][2] + bv.x;
            v1.y = acc[mt][nt][3] + bv.y;
            if (HAS_SKIP) {
                const float2 s0 = *(const float2*)(skip + (size_t)r0 * N + col);
                const float2 s1 = *(const float2*)(skip + (size_t)(r0 + 8) * N + col);
                v0.x += s0.x; v0.y += s0.y;
                v1.x += s1.x; v1.y += s1.y;
            }
            *(float2*)(C + (size_t)r0 * N + col)       = v0;
            *(float2*)(C + (size_t)(r0 + 8) * N + col) = v1;
        }
    }
}

// embed GEMM: A = patch gather from x
__global__ __launch_bounds__(256)
void gemm_embed(const float* __restrict__ x, const float* __restrict__ Bm,
                const float* __restrict__ bias, float* __restrict__ C) {
    extern __shared__ float sm[];
    gemm3_body<1, false>(sm, x, Bm, bias, nullptr, C, BSROWS, EE, EE,
                         blockIdx.y * 128, blockIdx.x * 128);
}

// fused QKV: grid.z selects which projection
__global__ __launch_bounds__(256)
void gemm_qkv(const float* __restrict__ h,
              const float* __restrict__ wq, const float* __restrict__ wk,
              const float* __restrict__ wv, const float* __restrict__ bq,
              const float* __restrict__ bk, const float* __restrict__ bv,
              float* __restrict__ q, float* __restrict__ k, float* __restrict__ v) {
    extern __shared__ float sm[];
    const int z = blockIdx.z;
    const float* w = (z == 0) ? wq : (z == 1) ? wk : wv;
    const float* b = (z == 0) ? bq : (z == 1) ? bk : bv;
    float* o       = (z == 0) ? q  : (z == 1) ? k  : v;
    gemm3_body<0, false>(sm, h, w, b, nullptr, o, BSROWS, EE, EE,
                         blockIdx.y * 128, blockIdx.x * 128);
}

// output projection + residual
__global__ __launch_bounds__(256)
void gemm_proj(const float* __restrict__ a, const float* __restrict__ w,
               const float* __restrict__ bias, const float* __restrict__ skip,
               float* __restrict__ C) {
    extern __shared__ float sm[];
    gemm3_body<0, true>(sm, a, w, bias, skip, C, BSROWS, EE, EE,
                        blockIdx.y * 128, blockIdx.x * 128);
}

// =================== attention scores: S = Q K^T / sqrt(HD) =================
__global__ __launch_bounds__(256)
void scores_mma(const float* __restrict__ q, const float* __restrict__ k,
                float* __restrict__ sc) {
    extern __shared__ float sm[];
    float* Asm = sm;
    float* Bsm = sm + 2 * TILEF;

    const int tid = threadIdx.x;
    const int wid = tid >> 5, lane = tid & 31;
    const int wm = wid >> 2, wn = wid & 3;
    const int gl = lane >> 2, tg = lane & 3;

    const int bh = blockIdx.z;
    const int b = bh >> 2, h = bh & 3;
    const int m0 = blockIdx.y * 128, n0 = blockIdx.x * 128;
    const int avalid = SS - m0;
    const int bvalid = SS - n0;

    const float* qb = q + (size_t)(b * SS) * EE + h * HD;
    const float* kb = k + (size_t)(b * SS) * EE + h * HD;
    float* cb = sc + (size_t)bh * SP * SP;

    const int srow = tid >> 3, sc4 = tid & 7;

    float acc[4][4][4];
#pragma unroll
    for (int i = 0; i < 4; i++)
#pragma unroll
        for (int j = 0; j < 4; j++)
#pragma unroll
            for (int r = 0; r < 4; r++) acc[i][j][r] = 0.f;

    const int NC = HD >> 5;

    auto stage = [&](int c, int buf) {
        float* ad = Asm + buf * TILEF;
        float* bd = Bsm + buf * TILEF;
#pragma unroll
        for (int i = 0; i < 4; i++) {
            int row = srow + i * 32;
            bool va = row < avalid, vb = row < bvalid;
            int ra = va ? (m0 + row) : 0;
            int rb = vb ? (n0 + row) : 0;
            cp16z(ad + row * LDSD + sc4 * 4, qb + (size_t)ra * EE + c * 32 + sc4 * 4, va);
            cp16z(bd + row * LDSD + sc4 * 4, kb + (size_t)rb * EE + c * 32 + sc4 * 4, vb);
        }
    };

    stage(0, 0);
    CP_COMMIT();
    for (int c = 0; c < NC; c++) {
        const int buf = c & 1;
        if (c + 1 < NC) { stage(c + 1, buf ^ 1); CP_COMMIT(); CP_WAIT1(); }
        else           { CP_WAIT0(); }
        __syncthreads();
        const float* As = Asm + buf * TILEF + (wm * 64) * LDSD;
        const float* Bs = Bsm + buf * TILEF + (wn * 32) * LDSD;
        MMA_CHUNK_COMPUTE(As, Bs);
        __syncthreads();
    }

    const float scale = 0.07216878364870322f;  // 1/sqrt(192)
#pragma unroll
    for (int mt = 0; mt < 4; mt++) {
        const int r0 = m0 + wm * 64 + mt * 16 + gl;
#pragma unroll
        for (int nt = 0; nt < 4; nt++) {
            const int col = n0 + wn * 32 + nt * 8 + tg * 2;
            if (col < SS) {
                if (r0 < SS) {
                    float2 v; v.x = acc[mt][nt][0] * scale; v.y = acc[mt][nt][1] * scale;
                    *(float2*)(cb + (size_t)r0 * SP + col) = v;
                }
                if (r0 + 8 < SS) {
                    float2 v; v.x = acc[mt][nt][2] * scale; v.y = acc[mt][nt][3] * scale;
                    *(float2*)(cb + (size_t)(r0 + 8) * SP + col) = v;
                }
            }
        }
    }
}

// =================== attention output: O = P @ V ============================
__global__ __launch_bounds__(256)
void attnout_mma(const float* __restrict__ sc, const float* __restrict__ vt,
                 float* __restrict__ o) {
    extern __shared__ float sm[];
    float* Asm = sm;
    float* Bsm = sm + 2 * TILEF;

    const int tid = threadIdx.x;
    const int wid = tid >> 5, lane = tid & 31;
    const int wm = wid >> 2, wn = wid & 3;
    const int gl = lane >> 2, tg = lane & 3;

    const int bh = blockIdx.z;
    const int b = bh >> 2, h = bh & 3;
    const int m0 = blockIdx.y * 128, n0 = blockIdx.x * 128;
    const int avalid = SS - m0;
    const int bvalid = HD - n0;

    const float* Ab = sc + (size_t)bh * SP * SP;
    const float* Bb = vt + (size_t)bh * HD * SP;
    float* ob = o + (size_t)(b * SS) * EE + h * HD;

    const int srow = tid >> 3, sc4 = tid & 7;

    float acc[4][4][4];
#pragma unroll
    for (int i = 0; i < 4; i++)
#pragma unroll
        for (int j = 0; j < 4; j++)
#pragma unroll
            for (int r = 0; r < 4; r++) acc[i][j][r] = 0.f;

    const int NC = SP >> 5;

    auto stage = [&](int c, int buf) {
        float* ad = Asm + buf * TILEF;
        float* bd = Bsm + buf * TILEF;
#pragma unroll
        for (int i = 0; i < 4; i++) {
            int row = srow + i * 32;
            bool va = row < avalid, vb = row < bvalid;
            int ra = va ? (m0 + row) : 0;
            int rb = vb ? (n0 + row) : 0;
            cp16z(ad + row * LDSD + sc4 * 4, Ab + (size_t)ra * SP + c * 32 + sc4 * 4, va);
            cp16z(bd + row * LDSD + sc4 * 4, Bb + (size_t)rb * SP + c * 32 + sc4 * 4, vb);
        }
    };

    stage(0, 0);
    CP_COMMIT();
    for (int c = 0; c < NC; c++) {
        const int buf = c & 1;
        if (c + 1 < NC) { stage(c + 1, buf ^ 1); CP_COMMIT(); CP_WAIT1(); }
        else           { CP_WAIT0(); }
        __syncthreads();
        const float* As = Asm + buf * TILEF + (wm * 64) * LDSD;
        const float* Bs = Bsm + buf * TILEF + (wn * 32) * LDSD;
        MMA_CHUNK_COMPUTE(As, Bs);
        __syncthreads();
    }

#pragma unroll
    for (int mt = 0; mt < 4; mt++) {
        const int r0 = m0 + wm * 64 + mt * 16 + gl;
#pragma unroll
        for (int nt = 0; nt < 4; nt++) {
            const int col = n0 + wn * 32 + nt * 8 + tg * 2;
            if (col < HD) {
                if (r0 < SS) {
                    float2 v; v.x = acc[mt][nt][0]; v.y = acc[mt][nt][1];
                    *(float2*)(ob + (size_t)r0 * EE + col) = v;
                }
                if (r0 + 8 < SS) {
                    float2 v; v.x = acc[mt][nt][2]; v.y = acc[mt][nt][3];
                    *(float2*)(ob + (size_t)(r0 + 8) * EE + col) = v;
                }
            }
        }
    }
}

// ---------------- V transpose: v[b,s,h,d] -> vt[bh][d][s padded] ------------
__global__ __launch_bounds__(256)
void vt_kernel(const float* __restrict__ v, float* __restrict__ vt) {
    __shared__ float t[32][33];
    const int bh = blockIdx.z;
    const int b = bh >> 2, h = bh & 3;
    const int s0 = blockIdx.x * 32, d0 = blockIdx.y * 32;
    const int tx = threadIdx.x & 31, ty = threadIdx.x >> 5;

    for (int i = ty; i < 32; i += 8) {
        int s = s0 + i, d = d0 + tx;
        float val = (s < SS) ? v[(size_t)(b * SS + s) * EE + h * HD + d] : 0.f;
        t[tx][i] = val;
    }
    __syncthreads();
    for (int i = ty; i < 32; i += 8) {
        int d = d0 + i, s = s0 + tx;
        vt[((size_t)bh * HD + d) * SP + s] = t[i][tx];
    }
}

// ---------------- LayerNorm over [S,E] per batch ---------------------------
__global__ __launch_bounds__(512)
void ln_reduce(const float* __restrict__ x, float* __restrict__ stats) {
    int b = blockIdx.x;
    const float4* p = (const float4*)(x + (size_t)b * SE);
    float s = 0.f, s2 = 0.f;
    for (int i = threadIdx.x; i < SE / 4; i += blockDim.x) {
        float4 v = p[i];
        s  += v.x + v.y + v.z + v.w;
        s2 += v.x * v.x + v.y * v.y + v.z * v.z + v.w * v.w;
    }
    __shared__ float sh[16], sh2[16];
#pragma unroll
    for (int o = 16; o > 0; o >>= 1) {
        s  += __shfl_xor_sync(0xffffffffu, s, o);
        s2 += __shfl_xor_sync(0xffffffffu, s2, o);
    }
    int w = threadIdx.x >> 5;
    if ((threadIdx.x & 31) == 0) { sh[w] = s; sh2[w] = s2; }
    __syncthreads();
    if (threadIdx.x == 0) {
        float ts = 0.f, ts2 = 0.f;
        for (int i = 0; i < 16; i++) { ts += sh[i]; ts2 += sh2[i]; }
        float mean = ts / (float)SE;
        float var  = ts2 / (float)SE - mean * mean;
        stats[2 * b] = mean;
        stats[2 * b + 1] = rsqrtf(var + LN_EPS);
    }
}

// float4-vectorized LN apply
__global__ __launch_bounds__(256)
void ln_apply4(const float4* __restrict__ x, const float4* __restrict__ w,
               const float4* __restrict__ bias, const float* __restrict__ stats,
               float4* __restrict__ out) {
    int idx = blockIdx.x * blockDim.x + threadIdx.x;
    if (idx >= BB * SE / 4) return;
    int b = idx / (SE / 4);
    int i = idx - b * (SE / 4);
    float mean = stats[2 * b], rstd = stats[2 * b + 1];
    float4 xv = x[idx], wv = w[i], bv = bias[i];
    float4 o;
    o.x = (xv.x - mean) * rstd * wv.x + bv.x;
    o.y = (xv.y - mean) * rstd * wv.y + bv.y;
    o.z = (xv.z - mean) * rstd * wv.z + bv.z;
    o.w = (xv.w - mean) * rstd * wv.w + bv.w;
    out[idx] = o;
}

// ---------------- softmax over rows of padded scores -----------------------
__global__ __launch_bounds__(128)
void softmax_k(float* __restrict__ sc) {
    const int bh = blockIdx.y;
    float* p = sc + (size_t)bh * SP * SP + (size_t)blockIdx.x * SP;
    int tid = threadIdx.x;
    __shared__ float redm[4], reds[4];

    float mx = -1e30f;
    for (int i = tid; i < SS; i += 128) mx = fmaxf(mx, p[i]);
#pragma unroll
    for (int o = 16; o > 0; o >>= 1) mx = fmaxf(mx, __shfl_xor_sync(0xffffffffu, mx, o));
    if ((tid & 31) == 0) redm[tid >> 5] = mx;
    __syncthreads();
    mx = fmaxf(fmaxf(redm[0], redm[1]), fmaxf(redm[2], redm[3]));

    float sum = 0.f;
    for (int i = tid; i < SS; i += 128) {
        float e = __expf(p[i] - mx);
        p[i] = e;
        sum += e;
    }
#pragma unroll
    for (int o = 16; o > 0; o >>= 1) sum += __shfl_xor_sync(0xffffffffu, sum, o);
    if ((tid & 31) == 0) reds[tid >> 5] = sum;
    __syncthreads();
    sum = reds[0] + reds[1] + reds[2] + reds[3];
    float inv = 1.0f / sum;
    for (int i = tid; i < SP; i += 128)
        p[i] = (i < SS) ? p[i] * inv : 0.f;
}

// ---------------- launch ----------------------------------------------------
extern "C" void kernel_launch(void* const* d_in, const int* in_sizes, int n_in,
                              void* d_out, int out_size) {
    const float* x      = (const float*)d_in[0];
    const float* conv_w = (const float*)d_in[1];
    const float* conv_b = (const float*)d_in[2];
    const float* wq     = (const float*)d_in[3];
    const float* bq     = (const float*)d_in[4];
    const float* wk     = (const float*)d_in[5];
    const float* bk     = (const float*)d_in[6];
    const float* wv     = (const float*)d_in[7];
    const float* bv     = (const float*)d_in[8];
    const float* wo     = (const float*)d_in[9];
    const float* bo     = (const float*)d_in[10];
    const float* ln1w   = (const float*)d_in[11];
    const float* ln1b   = (const float*)d_in[12];
    const float* ln2w   = (const float*)d_in[13];
    const float* ln2b   = (const float*)d_in[14];
    float* out = (float*)d_out;

    float *emb, *h, *q, *k, *v, *vt, *sc, *ao, *res, *stats;
    cudaGetSymbolAddress((void**)&emb,   g_emb);
    cudaGetSymbolAddress((void**)&h,     g_h);
    cudaGetSymbolAddress((void**)&q,     g_q);
    cudaGetSymbolAddress((void**)&k,     g_k);
    cudaGetSymbolAddress((void**)&v,     g_v);
    cudaGetSymbolAddress((void**)&vt,    g_vt);
    cudaGetSymbolAddress((void**)&sc,    g_scores);
    cudaGetSymbolAddress((void**)&ao,    g_attno);
    cudaGetSymbolAddress((void**)&res,   g_res);
    cudaGetSymbolAddress((void**)&stats, g_stats);

    cudaFuncSetAttribute(gemm_embed,
                         cudaFuncAttributeMaxDynamicSharedMemorySize, GEMM3_SMEM_BYTES);
    cudaFuncSetAttribute(gemm_qkv,
                         cudaFuncAttributeMaxDynamicSharedMemorySize, GEMM3_SMEM_BYTES);
    cudaFuncSetAttribute(gemm_proj,
                         cudaFuncAttributeMaxDynamicSharedMemorySize, GEMM3_SMEM_BYTES);
    cudaFuncSetAttribute(scores_mma,
                         cudaFuncAttributeMaxDynamicSharedMemorySize, GEMM2_SMEM_BYTES);
    cudaFuncSetAttribute(attnout_mma,
                         cudaFuncAttributeMaxDynamicSharedMemorySize, GEMM2_SMEM_BYTES);

    dim3 tc_grid(EE / 128, BSROWS / 128);       // (6, 98)
    dim3 qkv_grid(EE / 128, BSROWS / 128, 3);   // (6, 98, 3)

    // 1. patch embedding GEMM (fused patch gather)
    gemm_embed<<<tc_grid, 256, GEMM3_SMEM_BYTES>>>(x, conv_w, conv_b, emb);
    // 2. LN1
    ln_reduce<<<BB, 512>>>(emb, stats);
    ln_apply4<<<(BB * SE / 4 + 255) / 256, 256>>>((const float4*)emb, (const float4*)ln1w,
                                                  (const float4*)ln1b, stats, (float4*)h);
    // 3. QKV (single fused launch)
    gemm_qkv<<<qkv_grid, 256, GEMM3_SMEM_BYTES>>>(h, wq, wk, wv, bq, bk, bv, q, k, v);
    // 4. attention
    vt_kernel<<<dim3(SP / 32, HD / 32, BB * HH), 256>>>(v, vt);
    scores_mma<<<dim3(2, 2, BB * HH), 256, GEMM2_SMEM_BYTES>>>(q, k, sc);
    softmax_k<<<dim3(SS, BB * HH), 128>>>(sc);
    attnout_mma<<<dim3(2, 2, BB * HH), 256, GEMM2_SMEM_BYTES>>>(sc, vt, ao);
    // 5. output projection + residual
    gemm_proj<<<tc_grid, 256, GEMM3_SMEM_BYTES>>>(ao, wo, bo, emb, res);
    // 6. LN2 -> d_out
    ln_reduce<<<BB, 512>>>(res, stats);
    ln_apply4<<<(BB * SE / 4 + 255) / 256, 256>>>((const float4*)res, (const float4*)ln2w,
                                                  (const float4*)ln2b, stats, (float4*)out);
}

// round 9
// speedup vs baseline: 8.4582x; 1.0750x over previous
#include <cuda_runtime.h>
#include <math.h>
#include <stdint.h>

#define BB 64
#define SS 196
#define EE 768
#define HH 4
#define HD 192
#define SP 224              /* padded seq (196 -> 224 = 7*32) */
#define GRID14 14
#define BSROWS (BB*SS)      /* 12544 */
#define SE (SS*EE)          /* 150528 */
#define LN_EPS 1e-5f

// ---------------- scratch (static device arrays; no cudaMalloc) -------------
__device__ float g_emb[BSROWS*EE];      // skip1
__device__ float g_h[BSROWS*EE];        // LN1 output
__device__ float g_q[BSROWS*EE];
__device__ float g_k[BSROWS*EE];
__device__ float g_v[BSROWS*EE];
__device__ float g_vt[BB*HH*HD*SP];     // V transposed per head, s padded
__device__ float g_scores[BB*HH*SP*SP]; // padded scores/probs
__device__ float g_attno[BSROWS*EE];
__device__ float g_res[BSROWS*EE];      // skip1 + proj (pre-LN2)
__device__ float g_part[BB*4*2];        // partial LN sums
__device__ float g_stats[BB*2];         // mean, rstd per batch

// =================== helpers ================================================
__device__ __forceinline__ uint32_t smem_u32(const void* p) {
    uint32_t a;
    asm("{ .reg .u64 t; cvta.to.shared.u64 t, %1; cvt.u32.u64 %0, t; }"
        : "=r"(a) : "l"(p));
    return a;
}

__device__ __forceinline__ void cp16(void* smem_dst, const void* gmem_src) {
    uint32_t s = smem_u32(smem_dst);
    asm volatile("cp.async.cg.shared.global [%0], [%1], 16;"
                 :: "r"(s), "l"(gmem_src) : "memory");
}
__device__ __forceinline__ void cp16z(void* smem_dst, const void* gmem_src, bool v) {
    uint32_t s = smem_u32(smem_dst);
    int sz = v ? 16 : 0;
    asm volatile("cp.async.cg.shared.global [%0], [%1], 16, %2;"
                 :: "r"(s), "l"(gmem_src), "r"(sz) : "memory");
}
#define CP_COMMIT() asm volatile("cp.async.commit_group;" ::: "memory")
#define CP_WAIT0()  asm volatile("cp.async.wait_group 0;" ::: "memory")

// mma.sync m16n8k8 tf32: D(16x8,f32) += A(16x8,tf32) * B(8x8,tf32)
__device__ __forceinline__ void mma_tf32(float* c, const uint32_t* a,
                                         const uint32_t* b) {
    asm volatile(
        "mma.sync.aligned.m16n8k8.row.col.f32.tf32.tf32.f32 "
        "{%0,%1,%2,%3}, {%4,%5,%6,%7}, {%8,%9}, {%0,%1,%2,%3};"
        : "+f"(c[0]), "+f"(c[1]), "+f"(c[2]), "+f"(c[3])
        : "r"(a[0]), "r"(a[1]), "r"(a[2]), "r"(a[3]), "r"(b[0]), "r"(b[1]));
}

// =================== tile framework constants ===============================
#define LDSD 40                       /* padded row stride (floats); 40%32=8 -> */
                                      /* conflict-free LDS.64 fragment loads   */
#define TILEF (128 * LDSD)            /* 5120 floats per (A or B) buffer */
#define GEMM_SMEM_BYTES (4 * TILEF * 4)   /* 2 stages x (A+B) = 81920 B */

// Fragment loads use the k-permutation trick: thread tg's two k-slots are
// logical columns {kk+2tg, kk+2tg+1} (contiguous -> one LDS.64). Valid because
// the same permutation is applied to A and B.
#define MMA_CHUNK_COMPUTE(As, Bs)                                             \
    do {                                                                      \
        _Pragma("unroll")                                                     \
        for (int kk = 0; kk < 32; kk += 8) {                                  \
            uint32_t af[4][4], bf[4][2];                                      \
            _Pragma("unroll")                                                 \
            for (int mt = 0; mt < 4; mt++) {                                  \
                const float2 x0 = *(const float2*)((As) + (mt * 16 + gl) * LDSD + kk + 2 * tg); \
                const float2 x1 = *(const float2*)((As) + (mt * 16 + gl + 8) * LDSD + kk + 2 * tg); \
                af[mt][0] = __float_as_uint(x0.x);                            \
                af[mt][2] = __float_as_uint(x0.y);                            \
                af[mt][1] = __float_as_uint(x1.x);                            \
                af[mt][3] = __float_as_uint(x1.y);                            \
            }                                                                 \
            _Pragma("unroll")                                                 \
            for (int nt = 0; nt < 4; nt++) {                                  \
                const float2 y = *(const float2*)((Bs) + (nt * 8 + gl) * LDSD + kk + 2 * tg); \
                bf[nt][0] = __float_as_uint(y.x);                             \
                bf[nt][1] = __float_as_uint(y.y);                             \
            }                                                                 \
            _Pragma("unroll")                                                 \
            for (int mt = 0; mt < 4; mt++)                                    \
                _Pragma("unroll")                                             \
                for (int nt = 0; nt < 4; nt++)                                \
                    mma_tf32(acc[mt][nt], af[mt], bf[nt]);                    \
        }                                                                     \
    } while (0)

// patch-gather address: row m of the virtual patch matrix, column col
__device__ __forceinline__ const float* embed_addr(const float* x, int m, int col) {
    int b = m / SS, s = m - b * SS;
    int gy = s / GRID14, gx = s - gy * GRID14;
    int ch = col >> 8, r = col & 255;
    int py = r >> 4, px = r & 15;
    return x + (((size_t)(b * 3 + ch) * 224 + (gy * 16 + py)) * 224 + gx * 16 + px);
}

// =================== 2-stage tf32 GEMM body =================================
// C[M,N] = A[M,K]*B[N,K]^T + bias (+skip). M%128==0, N%128==0, K%32==0.
// MODE 0: A from gmem row-major.  MODE 1: A = patch-gather from image x.
template <int MODE, bool HAS_SKIP>
__device__ __forceinline__ void gemm_body(
    float* sm, const float* __restrict__ A, const float* __restrict__ Bm,
    const float* __restrict__ bias, const float* __restrict__ skip,
    float* __restrict__ C, int M, int N, int K, int m0, int n0) {
    const int tid = threadIdx.x;
    const int wid = tid >> 5, lane = tid & 31;
    const int wm = wid >> 2, wn = wid & 3;
    const int gl = lane >> 2, tg = lane & 3;
    const int srow = tid >> 3, sc4 = tid & 7;

    float acc[4][4][4];
#pragma unroll
    for (int i = 0; i < 4; i++)
#pragma unroll
        for (int j = 0; j < 4; j++)
#pragma unroll
            for (int r = 0; r < 4; r++) acc[i][j][r] = 0.f;

    const int NC = K >> 5;

    auto stage = [&](int c, int buf) {
        float* ad = sm + buf * (2 * TILEF);
        float* bd = ad + TILEF;
        const int colbase = c * 32 + sc4 * 4;
#pragma unroll
        for (int i = 0; i < 4; i++) {
            int row = srow + i * 32;
            const float* asrc;
            if (MODE == 1) asrc = embed_addr(A, m0 + row, colbase);
            else           asrc = A + (size_t)(m0 + row) * K + colbase;
            cp16(ad + row * LDSD + sc4 * 4, asrc);
            cp16(bd + row * LDSD + sc4 * 4, Bm + (size_t)(n0 + row) * K + colbase);
        }
    };

    stage(0, 0); CP_COMMIT();

    for (int c = 0; c < NC; c++) {
        CP_WAIT0();
        __syncthreads();
        if (c + 1 < NC) { stage(c + 1, (c + 1) & 1); CP_COMMIT(); }
        const int buf = c & 1;
        const float* As = sm + buf * (2 * TILEF) + (wm * 64) * LDSD;
        const float* Bs = sm + buf * (2 * TILEF) + TILEF + (wn * 32) * LDSD;
        MMA_CHUNK_COMPUTE(As, Bs);
    }

#pragma unroll
    for (int mt = 0; mt < 4; mt++) {
        const int r0 = m0 + wm * 64 + mt * 16 + gl;
#pragma unroll
        for (int nt = 0; nt < 4; nt++) {
            const int col = n0 + wn * 32 + nt * 8 + tg * 2;
            const float2 bv = *(const float2*)(bias + col);
            float2 v0, v1;
            v0.x = acc[mt][nt][0] + bv.x;
            v0.y = acc[mt][nt][1] + bv.y;
            v1.x = acc[mt][nt][2] + bv.x;
            v1.y = acc[mt][nt][3] + bv.y;
            if (HAS_SKIP) {
                const float2 s0 = *(const float2*)(skip + (size_t)r0 * N + col);
                const float2 s1 = *(const float2*)(skip + (size_t)(r0 + 8) * N + col);
                v0.x += s0.x; v0.y += s0.y;
                v1.x += s1.x; v1.y += s1.y;
            }
            *(float2*)(C + (size_t)r0 * N + col)       = v0;
            *(float2*)(C + (size_t)(r0 + 8) * N + col) = v1;
        }
    }
}

// embed GEMM: A = patch gather from x
__global__ __launch_bounds__(256)
void gemm_embed(const float* __restrict__ x, const float* __restrict__ Bm,
                const float* __restrict__ bias, float* __restrict__ C) {
    extern __shared__ float sm[];
    gemm_body<1, false>(sm, x, Bm, bias, nullptr, C, BSROWS, EE, EE,
                        blockIdx.y * 128, blockIdx.x * 128);
}

// fused QKV: grid.z selects which projection
__global__ __launch_bounds__(256)
void gemm_qkv(const float* __restrict__ h,
              const float* __restrict__ wq, const float* __restrict__ wk,
              const float* __restrict__ wv, const float* __restrict__ bq,
              const float* __restrict__ bk, const float* __restrict__ bv,
              float* __restrict__ q, float* __restrict__ k, float* __restrict__ v) {
    extern __shared__ float sm[];
    const int z = blockIdx.z;
    const float* w = (z == 0) ? wq : (z == 1) ? wk : wv;
    const float* b = (z == 0) ? bq : (z == 1) ? bk : bv;
    float* o       = (z == 0) ? q  : (z == 1) ? k  : v;
    gemm_body<0, false>(sm, h, w, b, nullptr, o, BSROWS, EE, EE,
                        blockIdx.y * 128, blockIdx.x * 128);
}

// output projection + residual
__global__ __launch_bounds__(256)
void gemm_proj(const float* __restrict__ a, const float* __restrict__ w,
               const float* __restrict__ bias, const float* __restrict__ skip,
               float* __restrict__ C) {
    extern __shared__ float sm[];
    gemm_body<0, true>(sm, a, w, bias, skip, C, BSROWS, EE, EE,
                       blockIdx.y * 128, blockIdx.x * 128);
}

// =================== attention scores: S = Q K^T / sqrt(HD) =================
__global__ __launch_bounds__(256)
void scores_mma(const float* __restrict__ q, const float* __restrict__ k,
                float* __restrict__ sc) {
    extern __shared__ float sm[];
    const int tid = threadIdx.x;
    const int wid = tid >> 5, lane = tid & 31;
    const int wm = wid >> 2, wn = wid & 3;
    const int gl = lane >> 2, tg = lane & 3;

    const int bh = blockIdx.z;
    const int b = bh >> 2, h = bh & 3;
    const int m0 = blockIdx.y * 128, n0 = blockIdx.x * 128;
    const int avalid = SS - m0;
    const int bvalid = SS - n0;

    const float* qb = q + (size_t)(b * SS) * EE + h * HD;
    const float* kb = k + (size_t)(b * SS) * EE + h * HD;
    float* cb = sc + (size_t)bh * SP * SP;

    const int srow = tid >> 3, sc4 = tid & 7;

    float acc[4][4][4];
#pragma unroll
    for (int i = 0; i < 4; i++)
#pragma unroll
        for (int j = 0; j < 4; j++)
#pragma unroll
            for (int r = 0; r < 4; r++) acc[i][j][r] = 0.f;

    const int NC = HD >> 5;

    auto stage = [&](int c, int buf) {
        float* ad = sm + buf * (2 * TILEF);
        float* bd = ad + TILEF;
#pragma unroll
        for (int i = 0; i < 4; i++) {
            int row = srow + i * 32;
            bool va = row < avalid, vb = row < bvalid;
            int ra = va ? (m0 + row) : 0;
            int rb = vb ? (n0 + row) : 0;
            cp16z(ad + row * LDSD + sc4 * 4, qb + (size_t)ra * EE + c * 32 + sc4 * 4, va);
            cp16z(bd + row * LDSD + sc4 * 4, kb + (size_t)rb * EE + c * 32 + sc4 * 4, vb);
        }
    };

    stage(0, 0); CP_COMMIT();
    for (int c = 0; c < NC; c++) {
        CP_WAIT0();
        __syncthreads();
        if (c + 1 < NC) { stage(c + 1, (c + 1) & 1); CP_COMMIT(); }
        const int buf = c & 1;
        const float* As = sm + buf * (2 * TILEF) + (wm * 64) * LDSD;
        const float* Bs = sm + buf * (2 * TILEF) + TILEF + (wn * 32) * LDSD;
        MMA_CHUNK_COMPUTE(As, Bs);
    }

    const float scale = 0.07216878364870322f;  // 1/sqrt(192)
#pragma unroll
    for (int mt = 0; mt < 4; mt++) {
        const int r0 = m0 + wm * 64 + mt * 16 + gl;
#pragma unroll
        for (int nt = 0; nt < 4; nt++) {
            const int col = n0 + wn * 32 + nt * 8 + tg * 2;
            if (col < SS) {
                if (r0 < SS) {
                    float2 v; v.x = acc[mt][nt][0] * scale; v.y = acc[mt][nt][1] * scale;
                    *(float2*)(cb + (size_t)r0 * SP + col) = v;
                }
                if (r0 + 8 < SS) {
                    float2 v; v.x = acc[mt][nt][2] * scale; v.y = acc[mt][nt][3] * scale;
                    *(float2*)(cb + (size_t)(r0 + 8) * SP + col) = v;
                }
            }
        }
    }
}

// =================== attention output: O = P @ V ============================
__global__ __launch_bounds__(256)
void attnout_mma(const float* __restrict__ sc, const float* __restrict__ vt,
                 float* __restrict__ o) {
    extern __shared__ float sm[];
    const int tid = threadIdx.x;
    const int wid = tid >> 5, lane = tid & 31;
    const int wm = wid >> 2, wn = wid & 3;
    const int gl = lane >> 2, tg = lane & 3;

    const int bh = blockIdx.z;
    const int b = bh >> 2, h = bh & 3;
    const int m0 = blockIdx.y * 128, n0 = blockIdx.x * 128;
    const int avalid = SS - m0;
    const int bvalid = HD - n0;

    const float* Ab = sc + (size_t)bh * SP * SP;
    const float* Bb = vt + (size_t)bh * HD * SP;
    float* ob = o + (size_t)(b * SS) * EE + h * HD;

    const int srow = tid >> 3, sc4 = tid & 7;

    float acc[4][4][4];
#pragma unroll
    for (int i = 0; i < 4; i++)
#pragma unroll
        for (int j = 0; j < 4; j++)
#pragma unroll
            for (int r = 0; r < 4; r++) acc[i][j][r] = 0.f;

    const int NC = SP >> 5;

    auto stage = [&](int c, int buf) {
        float* ad = sm + buf * (2 * TILEF);
        float* bd = ad + TILEF;
#pragma unroll
        for (int i = 0; i < 4; i++) {
            int row = srow + i * 32;
            bool va = row < avalid, vb = row < bvalid;
            int ra = va ? (m0 + row) : 0;
            int rb = vb ? (n0 + row) : 0;
            cp16z(ad + row * LDSD + sc4 * 4, Ab + (size_t)ra * SP + c * 32 + sc4 * 4, va);
            cp16z(bd + row * LDSD + sc4 * 4, Bb + (size_t)rb * SP + c * 32 + sc4 * 4, vb);
        }
    };

    stage(0, 0); CP_COMMIT();
    for (int c = 0; c < NC; c++) {
        CP_WAIT0();
        __syncthreads();
        if (c + 1 < NC) { stage(c + 1, (c + 1) & 1); CP_COMMIT(); }
        const int buf = c & 1;
        const float* As = sm + buf * (2 * TILEF) + (wm * 64) * LDSD;
        const float* Bs = sm + buf * (2 * TILEF) + TILEF + (wn * 32) * LDSD;
        MMA_CHUNK_COMPUTE(As, Bs);
    }

#pragma unroll
    for (int mt = 0; mt < 4; mt++) {
        const int r0 = m0 + wm * 64 + mt * 16 + gl;
#pragma unroll
        for (int nt = 0; nt < 4; nt++) {
            const int col = n0 + wn * 32 + nt * 8 + tg * 2;
            if (col < HD) {
                if (r0 < SS) {
                    float2 v; v.x = acc[mt][nt][0]; v.y = acc[mt][nt][1];
                    *(float2*)(ob + (size_t)r0 * EE + col) = v;
                }
                if (r0 + 8 < SS) {
                    float2 v; v.x = acc[mt][nt][2]; v.y = acc[mt][nt][3];
                    *(float2*)(ob + (size_t)(r0 + 8) * EE + col) = v;
                }
            }
        }
    }
}

// ---------------- V transpose: v[b,s,h,d] -> vt[bh][d][s padded] ------------
__global__ __launch_bounds__(256)
void vt_kernel(const float* __restrict__ v, float* __restrict__ vt) {
    __shared__ float t[32][33];
    const int bh = blockIdx.z;
    const int b = bh >> 2, h = bh & 3;
    const int s0 = blockIdx.x * 32, d0 = blockIdx.y * 32;
    const int tx = threadIdx.x & 31, ty = threadIdx.x >> 5;

    for (int i = ty; i < 32; i += 8) {
        int s = s0 + i, d = d0 + tx;
        float val = (s < SS) ? v[(size_t)(b * SS + s) * EE + h * HD + d] : 0.f;
        t[tx][i] = val;
    }
    __syncthreads();
    for (int i = ty; i < 32; i += 8) {
        int d = d0 + i, s = s0 + tx;
        vt[((size_t)bh * HD + d) * SP + s] = t[i][tx];
    }
}

// ---------------- LayerNorm over [S,E] per batch ---------------------------
// pass 1: 4 partial (sum, sumsq) per batch -> g_part; pass 2: finalize stats
__global__ __launch_bounds__(256)
void ln_reduce_part(const float* __restrict__ x, float* __restrict__ part) {
    const int b = blockIdx.y, j = blockIdx.x;   // j in [0,4)
    const int Q = SE / 16;                      // float4 per quarter (9408)
    const float4* p = (const float4*)(x + (size_t)b * SE) + j * Q;
    float s = 0.f, s2 = 0.f;
    for (int i = threadIdx.x; i < Q; i += 256) {
        float4 v = p[i];
        s  += v.x + v.y + v.z + v.w;
        s2 += v.x * v.x + v.y * v.y + v.z * v.z + v.w * v.w;
    }
    __shared__ float sh[8], sh2[8];
#pragma unroll
    for (int o = 16; o > 0; o >>= 1) {
        s  += __shfl_xor_sync(0xffffffffu, s, o);
        s2 += __shfl_xor_sync(0xffffffffu, s2, o);
    }
    int w = threadIdx.x >> 5;
    if ((threadIdx.x & 31) == 0) { sh[w] = s; sh2[w] = s2; }
    __syncthreads();
    if (threadIdx.x == 0) {
        float ts = 0.f, ts2 = 0.f;
#pragma unroll
        for (int i = 0; i < 8; i++) { ts += sh[i]; ts2 += sh2[i]; }
        part[(b * 4 + j) * 2]     = ts;
        part[(b * 4 + j) * 2 + 1] = ts2;
    }
}

__global__ void ln_finalize(const float* __restrict__ part, float* __restrict__ stats) {
    int b = threadIdx.x;
    if (b >= BB) return;
    float s = 0.f, s2 = 0.f;
#pragma unroll
    for (int j = 0; j < 4; j++) {
        s  += part[(b * 4 + j) * 2];
        s2 += part[(b * 4 + j) * 2 + 1];
    }
    float mean = s / (float)SE;
    float var  = s2 / (float)SE - mean * mean;
    stats[2 * b]     = mean;
    stats[2 * b + 1] = rsqrtf(var + LN_EPS);
}

// float4-vectorized LN apply
__global__ __launch_bounds__(256)
void ln_apply4(const float4* __restrict__ x, const float4* __restrict__ w,
               const float4* __restrict__ bias, const float* __restrict__ stats,
               float4* __restrict__ out) {
    int idx = blockIdx.x * blockDim.x + threadIdx.x;
    if (idx >= BB * SE / 4) return;
    int b = idx / (SE / 4);
    int i = idx - b * (SE / 4);
    float mean = stats[2 * b], rstd = stats[2 * b + 1];
    float4 xv = x[idx], wv = w[i], bv = bias[i];
    float4 o;
    o.x = (xv.x - mean) * rstd * wv.x + bv.x;
    o.y = (xv.y - mean) * rstd * wv.y + bv.y;
    o.z = (xv.z - mean) * rstd * wv.z + bv.z;
    o.w = (xv.w - mean) * rstd * wv.w + bv.w;
    out[idx] = o;
}

// ---------------- softmax over rows of padded scores -----------------------
__global__ __launch_bounds__(128)
void softmax_k(float* __restrict__ sc) {
    const int bh = blockIdx.y;
    float* p = sc + (size_t)bh * SP * SP + (size_t)blockIdx.x * SP;
    int tid = threadIdx.x;
    __shared__ float redm[4], reds[4];

    float mx = -1e30f;
    for (int i = tid; i < SS; i += 128) mx = fmaxf(mx, p[i]);
#pragma unroll
    for (int o = 16; o > 0; o >>= 1) mx = fmaxf(mx, __shfl_xor_sync(0xffffffffu, mx, o));
    if ((tid & 31) == 0) redm[tid >> 5] = mx;
    __syncthreads();
    mx = fmaxf(fmaxf(redm[0], redm[1]), fmaxf(redm[2], redm[3]));

    float sum = 0.f;
    for (int i = tid; i < SS; i += 128) {
        float e = __expf(p[i] - mx);
        p[i] = e;
        sum += e;
    }
#pragma unroll
    for (int o = 16; o > 0; o >>= 1) sum += __shfl_xor_sync(0xffffffffu, sum, o);
    if ((tid & 31) == 0) reds[tid >> 5] = sum;
    __syncthreads();
    sum = reds[0] + reds[1] + reds[2] + reds[3];
    float inv = 1.0f / sum;
    for (int i = tid; i < SP; i += 128)
        p[i] = (i < SS) ? p[i] * inv : 0.f;
}

// ---------------- launch ----------------------------------------------------
extern "C" void kernel_launch(void* const* d_in, const int* in_sizes, int n_in,
                              void* d_out, int out_size) {
    const float* x      = (const float*)d_in[0];
    const float* conv_w = (const float*)d_in[1];
    const float* conv_b = (const float*)d_in[2];
    const float* wq     = (const float*)d_in[3];
    const float* bq     = (const float*)d_in[4];
    const float* wk     = (const float*)d_in[5];
    const float* bk     = (const float*)d_in[6];
    const float* wv     = (const float*)d_in[7];
    const float* bv     = (const float*)d_in[8];
    const float* wo     = (const float*)d_in[9];
    const float* bo     = (const float*)d_in[10];
    const float* ln1w   = (const float*)d_in[11];
    const float* ln1b   = (const float*)d_in[12];
    const float* ln2w   = (const float*)d_in[13];
    const float* ln2b   = (const float*)d_in[14];
    float* out = (float*)d_out;

    float *emb, *h, *q, *k, *v, *vt, *sc, *ao, *res, *part, *stats;
    cudaGetSymbolAddress((void**)&emb,   g_emb);
    cudaGetSymbolAddress((void**)&h,     g_h);
    cudaGetSymbolAddress((void**)&q,     g_q);
    cudaGetSymbolAddress((void**)&k,     g_k);
    cudaGetSymbolAddress((void**)&v,     g_v);
    cudaGetSymbolAddress((void**)&vt,    g_vt);
    cudaGetSymbolAddress((void**)&sc,    g_scores);
    cudaGetSymbolAddress((void**)&ao,    g_attno);
    cudaGetSymbolAddress((void**)&res,   g_res);
    cudaGetSymbolAddress((void**)&part,  g_part);
    cudaGetSymbolAddress((void**)&stats, g_stats);

    cudaFuncSetAttribute(gemm_embed,
                         cudaFuncAttributeMaxDynamicSharedMemorySize, GEMM_SMEM_BYTES);
    cudaFuncSetAttribute(gemm_qkv,
                         cudaFuncAttributeMaxDynamicSharedMemorySize, GEMM_SMEM_BYTES);
    cudaFuncSetAttribute(gemm_proj,
                         cudaFuncAttributeMaxDynamicSharedMemorySize, GEMM_SMEM_BYTES);
    cudaFuncSetAttribute(scores_mma,
                         cudaFuncAttributeMaxDynamicSharedMemorySize, GEMM_SMEM_BYTES);
    cudaFuncSetAttribute(attnout_mma,
                         cudaFuncAttributeMaxDynamicSharedMemorySize, GEMM_SMEM_BYTES);

    dim3 tc_grid(EE / 128, BSROWS / 128);       // (6, 98)
    dim3 qkv_grid(EE / 128, BSROWS / 128, 3);   // (6, 98, 3)
    dim3 lnr_grid(4, BB);

    // 1. patch embedding GEMM (fused patch gather)
    gemm_embed<<<tc_grid, 256, GEMM_SMEM_BYTES>>>(x, conv_w, conv_b, emb);
    // 2. LN1
    ln_reduce_part<<<lnr_grid, 256>>>(emb, part);
    ln_finalize<<<1, 64>>>(part, stats);
    ln_apply4<<<(BB * SE / 4 + 255) / 256, 256>>>((const float4*)emb, (const float4*)ln1w,
                                                  (const float4*)ln1b, stats, (float4*)h);
    // 3. QKV (single fused launch)
    gemm_qkv<<<qkv_grid, 256, GEMM_SMEM_BYTES>>>(h, wq, wk, wv, bq, bk, bv, q, k, v);
    // 4. attention
    vt_kernel<<<dim3(SP / 32, HD / 32, BB * HH), 256>>>(v, vt);
    scores_mma<<<dim3(2, 2, BB * HH), 256, GEMM_SMEM_BYTES>>>(q, k, sc);
    softmax_k<<<dim3(SS, BB * HH), 128>>>(sc);
    attnout_mma<<<dim3(2, 2, BB * HH), 256, GEMM_SMEM_BYTES>>>(sc, vt, ao);
    // 5. output projection + residual
    gemm_proj<<<tc_grid, 256, GEMM_SMEM_BYTES>>>(ao, wo, bo, emb, res);
    // 6. LN2 -> d_out
    ln_reduce_part<<<lnr_grid, 256>>>(res, part);
    ln_finalize<<<1, 64>>>(part, stats);
    ln_apply4<<<(BB * SE / 4 + 255) / 256, 256>>>((const float4*)res, (const float4*)ln2w,
                                                  (const float4*)ln2b, stats, (float4*)out);
}